// round 3
// baseline (speedup 1.0000x reference)
#include <cuda_runtime.h>

#define Bdim 64
#define Hdim 64
#define Wdim 64
#define Cch  16
#define Fch  128
#define Dch  256
#define NPIX (Bdim * Hdim * Wdim)
#define TSTEPS 60

typedef unsigned long long u64;

__device__ float g_bufs[2][NPIX * Cch];

// ---- f32x2 packed helpers ----
__device__ __forceinline__ u64 pack2(float lo, float hi) {
    u64 r; asm("mov.b64 %0, {%1, %2};" : "=l"(r) : "f"(lo), "f"(hi)); return r;
}
__device__ __forceinline__ u64 dup2(float v) { return pack2(v, v); }
__device__ __forceinline__ void unpack2(u64 v, float& lo, float& hi) {
    asm("mov.b64 {%0, %1}, %2;" : "=f"(lo), "=f"(hi) : "l"(v));
}
__device__ __forceinline__ u64 fma2(u64 a, u64 b, u64 c) {
    u64 d; asm("fma.rn.f32x2 %0, %1, %2, %3;" : "=l"(d) : "l"(a), "l"(b), "l"(c)); return d;
}

// ---- shared layout (float indices) ----
#define S_IN  0                      // halo: 4 rows x 66 cols x 16 ch = 4224
#define S_WA  4224                   // 18432 floats: convW -> w1 chunks -> d2 partials
#define S_H   (4224 + 18432)         // conv out: 128 px x 128 = 16384
#define S_W2  (S_H + 16384)          // w2 pairs padded: 256 x 9 u64 = 4608 floats
#define SMEM_FLOATS (S_W2 + 4608)    // 43648 floats = 174592 B

__global__ void nca_init(const float* __restrict__ input) {
    int pix = blockIdx.x * blockDim.x + threadIdx.x;
    if (pix < NPIX) {
        float* g = g_bufs[0] + (size_t)pix * Cch;
        g[0] = input[pix];
        #pragma unroll
        for (int c = 1; c < Cch; c++) g[c] = 0.0f;
    }
}

// One CTA = 2 image rows = 128 pixels. 256 threads = 16(tx) x 16(ty).
// Thread (tx,ty): pixels p = 8*ty+i (i<8); conv pair-cols tx+16j (j<4);
// dense1 pair-cols tx+16j (j<8).
__global__ __launch_bounds__(256, 1) void nca_step(
    int sb,
    const float* __restrict__ cw, const float* __restrict__ cb,
    const float* __restrict__ w1, const float* __restrict__ b1,
    const float* __restrict__ w2, const float* __restrict__ b2)
{
    extern __shared__ float sm[];
    const float* __restrict__ gsrc = g_bufs[sb];
    float* __restrict__ gdst = g_bufs[sb ^ 1];

    const int tid = threadIdx.x;
    const int tx = tid & 15;
    const int ty = tid >> 4;
    const int b  = blockIdx.x >> 5;
    const int h0 = (blockIdx.x & 31) * 2;
    const int r  = ty >> 3;          // image row within CTA (0/1)
    const int w0 = (ty & 7) * 8;     // first pixel col of this thread

    // ---- Stage halo tile (rows h0-1..h0+2, cols -1..64, zero-padded) ----
    {
        float4* s4 = (float4*)(sm + S_IN);
        const float4* g4 = (const float4*)gsrc;
        #pragma unroll
        for (int idx = tid; idx < 4 * 66 * 4; idx += 256) {
            int rr  = idx / (66 * 4);
            int rem = idx - rr * (66 * 4);
            int wc  = rem >> 2;
            int c4  = rem & 3;
            int hh = h0 + rr - 1;
            int ww = wc - 1;
            float4 v = make_float4(0.f, 0.f, 0.f, 0.f);
            if (hh >= 0 && hh < Hdim && ww >= 0 && ww < Wdim)
                v = g4[(size_t)((b * Hdim + hh) * Wdim + ww) * 4 + c4];
            s4[idx] = v;
        }
    }
    // ---- Stage all conv weights (4608 float4) into S_WA ----
    {
        float4* s4 = (float4*)(sm + S_WA);
        const float4* g4 = (const float4*)cw;
        #pragma unroll
        for (int u = 0; u < 18; u++) s4[tid + 256 * u] = g4[tid + 256 * u];
    }
    // ---- Stage w2 as padded pairs: dst[k*9 + c'] = w2 pair (k, 2c') ----
    {
        u64* dst = (u64*)(sm + S_W2);
        const u64* src = (const u64*)w2;
        #pragma unroll
        for (int u = 0; u < 8; u++) {
            int idx = tid + 256 * u;
            int k = idx >> 3, c = idx & 7;
            dst[k * 9 + c] = src[idx];
        }
    }
    __syncthreads();

    // ============ Conv 3x3, 16 -> 128: 8px x 4 pair-cols ============
    u64 accC[8][4];
    {
        const u64* cbp = (const u64*)cb;
        #pragma unroll
        for (int j = 0; j < 4; j++) {
            u64 bj = __ldg(cbp + tx + 16 * j);
            #pragma unroll
            for (int i = 0; i < 8; i++) accC[i][j] = bj;
        }
    }
    #pragma unroll
    for (int tap = 0; tap < 9; tap++) {
        const int ky = tap / 3, kx = tap % 3;
        const float* abase = sm + S_IN + ((r + ky) * 66 + w0 + kx) * 16;
        const u64*  bbase = (const u64*)(sm + S_WA + tap * 16 * 128);
        #pragma unroll
        for (int cig = 0; cig < 4; cig++) {
            float4 a4[8];
            #pragma unroll
            for (int i = 0; i < 8; i++)
                a4[i] = *(const float4*)(abase + i * 16 + cig * 4);
            #pragma unroll
            for (int q = 0; q < 4; q++) {
                const u64* brow = bbase + (cig * 4 + q) * 64 + tx;
                u64 b0 = brow[0], b1v = brow[16], b2v = brow[32], b3v = brow[48];
                const float* af;
                #pragma unroll
                for (int i = 0; i < 8; i++) {
                    af = (const float*)&a4[i];
                    u64 av = dup2(af[q]);
                    accC[i][0] = fma2(av, b0,  accC[i][0]);
                    accC[i][1] = fma2(av, b1v, accC[i][1]);
                    accC[i][2] = fma2(av, b2v, accC[i][2]);
                    accC[i][3] = fma2(av, b3v, accC[i][3]);
                }
            }
        }
    }
    // h = relu(conv) -> S_H as [px][64 u64]
    {
        u64* hp = (u64*)(sm + S_H);
        #pragma unroll
        for (int i = 0; i < 8; i++) {
            int p = 8 * ty + i;
            #pragma unroll
            for (int j = 0; j < 4; j++) {
                float lo, hi; unpack2(accC[i][j], lo, hi);
                hp[p * 64 + tx + 16 * j] = pack2(fmaxf(lo, 0.f), fmaxf(hi, 0.f));
            }
        }
    }

    // ============ Dense1: 128 -> 256: 8px x 8 pair-cols ============
    u64 acc1[8][8];
    {
        const u64* b1p = (const u64*)b1;
        #pragma unroll
        for (int j = 0; j < 8; j++) {
            u64 bj = __ldg(b1p + tx + 16 * j);
            #pragma unroll
            for (int i = 0; i < 8; i++) acc1[i][j] = bj;
        }
    }
    #pragma unroll
    for (int kc = 0; kc < 2; kc++) {
        __syncthreads();   // convW / previous w1 chunk dead
        {   // stage w1[kc*64 .. +64][256] = 4096 float4
            float4* s4 = (float4*)(sm + S_WA);
            const float4* g4 = (const float4*)(w1 + kc * 64 * Dch);
            #pragma unroll
            for (int u = 0; u < 16; u++) s4[tid + 256 * u] = g4[tid + 256 * u];
        }
        __syncthreads();
        const u64* h2 = (const u64*)(sm + S_H) + (8 * ty) * 64 + kc * 32;
        #pragma unroll 4
        for (int kk2 = 0; kk2 < 32; kk2++) {
            u64 alo[8], ahi[8];
            #pragma unroll
            for (int i = 0; i < 8; i++) {
                u64 a2 = h2[i * 64 + kk2];
                float lo, hi; unpack2(a2, lo, hi);
                alo[i] = dup2(lo); ahi[i] = dup2(hi);
            }
            const u64* br0 = (const u64*)(sm + S_WA) + (2 * kk2) * 128 + tx;
            const u64* br1 = br0 + 128;
            #pragma unroll
            for (int j = 0; j < 8; j++) {
                u64 bv0 = br0[16 * j];
                u64 bv1 = br1[16 * j];
                #pragma unroll
                for (int i = 0; i < 8; i++) {
                    acc1[i][j] = fma2(alo[i], bv0, acc1[i][j]);
                    acc1[i][j] = fma2(ahi[i], bv1, acc1[i][j]);
                }
            }
        }
    }
    // relu in place
    #pragma unroll
    for (int i = 0; i < 8; i++)
        #pragma unroll
        for (int j = 0; j < 8; j++) {
            float lo, hi; unpack2(acc1[i][j], lo, hi);
            acc1[i][j] = pack2(fmaxf(lo, 0.f), fmaxf(hi, 0.f));
        }

    __syncthreads();   // w1 chunk dead; S_WA becomes partial region

    // ============ Dense2 fused, two c-halves of 8 channels ============
    #pragma unroll
    for (int ch = 0; ch < 2; ch++) {
        u64 acc2[8][4];
        #pragma unroll
        for (int i = 0; i < 8; i++)
            #pragma unroll
            for (int cp = 0; cp < 4; cp++) acc2[i][cp] = 0ull;

        #pragma unroll
        for (int j = 0; j < 8; j++) {
            float alo[8], ahi[8];
            #pragma unroll
            for (int i = 0; i < 8; i++) unpack2(acc1[i][j], alo[i], ahi[i]);
            const int k0 = 2 * tx + 32 * j;
            const u64* w2r0 = (const u64*)(sm + S_W2) + k0 * 9 + ch * 4;
            const u64* w2r1 = w2r0 + 9;
            u64 w00 = w2r0[0], w01 = w2r0[1], w02 = w2r0[2], w03 = w2r0[3];
            u64 w10 = w2r1[0], w11 = w2r1[1], w12 = w2r1[2], w13 = w2r1[3];
            #pragma unroll
            for (int i = 0; i < 8; i++) {
                u64 av0 = dup2(alo[i]);
                u64 av1 = dup2(ahi[i]);
                acc2[i][0] = fma2(av0, w00, acc2[i][0]);
                acc2[i][1] = fma2(av0, w01, acc2[i][1]);
                acc2[i][2] = fma2(av0, w02, acc2[i][2]);
                acc2[i][3] = fma2(av0, w03, acc2[i][3]);
                acc2[i][0] = fma2(av1, w10, acc2[i][0]);
                acc2[i][1] = fma2(av1, w11, acc2[i][1]);
                acc2[i][2] = fma2(av1, w12, acc2[i][2]);
                acc2[i][3] = fma2(av1, w13, acc2[i][3]);
            }
        }
        // write partials: part[(p*4+cp)*17 + tx] (u64)
        {
            u64* part = (u64*)(sm + S_WA);
            #pragma unroll
            for (int i = 0; i < 8; i++) {
                int p = 8 * ty + i;
                #pragma unroll
                for (int cp = 0; cp < 4; cp++)
                    part[(p * 4 + cp) * 17 + tx] = acc2[i][cp];
            }
        }
        __syncthreads();
        // reduce: 4 outputs per thread (1024 outputs per half)
        {
            const float* pf = sm + S_WA;
            #pragma unroll
            for (int o = 0; o < 4; o++) {
                int out = tid * 4 + o;
                int px = out >> 3, c8 = out & 7;
                int c = ch * 8 + c8;
                int cp = c8 >> 1, comp = c8 & 1;
                int base = ((px * 4 + cp) * 17) * 2 + comp;
                float s = 0.0f;
                #pragma unroll
                for (int g = 0; g < 16; g++) s += pf[base + 2 * g];
                int rr = px >> 6, ww = px & 63;
                const float* ctr = sm + S_IN + ((1 + rr) * 66 + ww + 1) * 16;
                float oldv = ctr[c];
                float nv = oldv;
                if (c != 0 && ctr[0] > 0.1f) nv += s + __ldg(b2 + c);
                gdst[((size_t)((b * Hdim + h0 + rr) * Wdim + ww)) * Cch + c] = nv;
            }
        }
        __syncthreads();   // before next half overwrites partials
    }
}

__global__ void nca_softmax(float* __restrict__ out) {
    int pix = blockIdx.x * blockDim.x + threadIdx.x;
    if (pix >= NPIX) return;
    const float* g = g_bufs[0] + (size_t)pix * Cch;
    float v[10];
    #pragma unroll
    for (int c = 0; c < 10; c++) v[c] = g[1 + c];
    float mx = v[0];
    #pragma unroll
    for (int c = 1; c < 10; c++) mx = fmaxf(mx, v[c]);
    float s = 0.0f;
    #pragma unroll
    for (int c = 0; c < 10; c++) { v[c] = __expf(v[c] - mx); s += v[c]; }
    float inv = 1.0f / s;
    float* o = out + (size_t)pix * 10;
    #pragma unroll
    for (int c = 0; c < 10; c++) o[c] = v[c] * inv;
}

extern "C" void kernel_launch(void* const* d_in, const int* in_sizes, int n_in,
                              void* d_out, int out_size) {
    const float* input = (const float*)d_in[0];
    const float* cw    = (const float*)d_in[1];
    const float* cb    = (const float*)d_in[2];
    const float* w1    = (const float*)d_in[3];
    const float* b1    = (const float*)d_in[4];
    const float* w2    = (const float*)d_in[5];
    const float* b2    = (const float*)d_in[6];

    const int smem_bytes = SMEM_FLOATS * 4;  // 174592 B
    cudaFuncSetAttribute(nca_step, cudaFuncAttributeMaxDynamicSharedMemorySize, smem_bytes);

    nca_init<<<NPIX / 256, 256>>>(input);
    for (int t = 0; t < TSTEPS; t++) {
        nca_step<<<Bdim * (Hdim / 2), 256, smem_bytes>>>(t & 1, cw, cb, w1, b1, w2, b2);
    }
    nca_softmax<<<NPIX / 256, 256>>>((float*)d_out);
}

// round 4
// speedup vs baseline: 1.0270x; 1.0270x over previous
#include <cuda_runtime.h>

#define Bdim 64
#define Hdim 64
#define Wdim 64
#define Cch  16
#define Fch  128
#define Dch  256
#define NPIX (Bdim * Hdim * Wdim)
#define TSTEPS 60

typedef unsigned long long u64;

__device__ float g_bufs[2][NPIX * Cch];

// ---- f32x2 packed helpers ----
__device__ __forceinline__ u64 pack2(float lo, float hi) {
    u64 r; asm("mov.b64 %0, {%1, %2};" : "=l"(r) : "f"(lo), "f"(hi)); return r;
}
__device__ __forceinline__ u64 dup2(float v) { return pack2(v, v); }
__device__ __forceinline__ void unpack2(u64 v, float& lo, float& hi) {
    asm("mov.b64 {%0, %1}, %2;" : "=f"(lo), "=f"(hi) : "l"(v));
}
__device__ __forceinline__ u64 fma2(u64 a, u64 b, u64 c) {
    u64 d; asm("fma.rn.f32x2 %0, %1, %2, %3;" : "=l"(d) : "l"(a), "l"(b), "l"(c)); return d;
}

// ---- shared layout (float indices) ----
#define S_IN  0                      // halo: 4 rows x 66 cols x 16 ch = 4224
#define S_WA  4224                   // 18432 floats: convW -> w1 chunks -> d2 partials
#define S_H   (4224 + 18432)         // conv out: 128 px x 128 = 16384
#define S_W2  (S_H + 16384)          // w2 pairs padded: 256 x 9 u64 = 4608 floats
#define SMEM_FLOATS (S_W2 + 4608)    // 43648 floats = 174592 B

__global__ void nca_init(const float* __restrict__ input) {
    int pix = blockIdx.x * blockDim.x + threadIdx.x;
    if (pix < NPIX) {
        float* g = g_bufs[0] + (size_t)pix * Cch;
        g[0] = input[pix];
        #pragma unroll
        for (int c = 1; c < Cch; c++) g[c] = 0.0f;
    }
}

// One CTA = 2 image rows = 128 pixels. 256 threads = 16(tx) x 16(ty).
// Thread (tx,ty): pixels p = 8*ty+i (i<8); conv pair-cols tx+16j (j<4);
// dense1 pair-cols tx+16j (j<8).
__global__ __launch_bounds__(256, 1) void nca_step(
    int sb,
    const float* __restrict__ cw, const float* __restrict__ cb,
    const float* __restrict__ w1, const float* __restrict__ b1,
    const float* __restrict__ w2, const float* __restrict__ b2)
{
    extern __shared__ float sm[];
    const float* __restrict__ gsrc = g_bufs[sb];
    float* __restrict__ gdst = g_bufs[sb ^ 1];

    const int tid = threadIdx.x;
    const int tx = tid & 15;
    const int ty = tid >> 4;
    const int b  = blockIdx.x >> 5;
    const int h0 = (blockIdx.x & 31) * 2;
    const int r  = ty >> 3;          // image row within CTA (0/1)
    const int w0 = (ty & 7) * 8;     // first pixel col of this thread

    // ---- Stage halo tile (rows h0-1..h0+2, cols -1..64, zero-padded) ----
    {
        float4* s4 = (float4*)(sm + S_IN);
        const float4* g4 = (const float4*)gsrc;
        #pragma unroll
        for (int idx = tid; idx < 4 * 66 * 4; idx += 256) {
            int rr  = idx / (66 * 4);
            int rem = idx - rr * (66 * 4);
            int wc  = rem >> 2;
            int c4  = rem & 3;
            int hh = h0 + rr - 1;
            int ww = wc - 1;
            float4 v = make_float4(0.f, 0.f, 0.f, 0.f);
            if (hh >= 0 && hh < Hdim && ww >= 0 && ww < Wdim)
                v = g4[(size_t)((b * Hdim + hh) * Wdim + ww) * 4 + c4];
            s4[idx] = v;
        }
    }
    // ---- Stage all conv weights (4608 float4) into S_WA ----
    {
        float4* s4 = (float4*)(sm + S_WA);
        const float4* g4 = (const float4*)cw;
        #pragma unroll
        for (int u = 0; u < 18; u++) s4[tid + 256 * u] = g4[tid + 256 * u];
    }
    // ---- Stage w2 as padded pairs: dst[k*9 + c'] = w2 pair (k, 2c') ----
    {
        u64* dst = (u64*)(sm + S_W2);
        const u64* src = (const u64*)w2;
        #pragma unroll
        for (int u = 0; u < 8; u++) {
            int idx = tid + 256 * u;
            int k = idx >> 3, c = idx & 7;
            dst[k * 9 + c] = src[idx];
        }
    }
    __syncthreads();

    // ============ Conv 3x3, 16 -> 128: 8px x 4 pair-cols ============
    u64 accC[8][4];
    {
        const u64* cbp = (const u64*)cb;
        #pragma unroll
        for (int j = 0; j < 4; j++) {
            u64 bj = __ldg(cbp + tx + 16 * j);
            #pragma unroll
            for (int i = 0; i < 8; i++) accC[i][j] = bj;
        }
    }
    #pragma unroll
    for (int tap = 0; tap < 9; tap++) {
        const int ky = tap / 3, kx = tap % 3;
        const float* abase = sm + S_IN + ((r + ky) * 66 + w0 + kx) * 16;
        const u64*  bbase = (const u64*)(sm + S_WA + tap * 16 * 128);
        #pragma unroll
        for (int cig = 0; cig < 4; cig++) {
            // B-stationary: 16 pairs (4 ci x 4 j) live in registers
            u64 breg[4][4];
            #pragma unroll
            for (int q = 0; q < 4; q++)
                #pragma unroll
                for (int j = 0; j < 4; j++)
                    breg[q][j] = bbase[(cig * 4 + q) * 64 + tx + 16 * j];
            #pragma unroll
            for (int i = 0; i < 8; i++) {
                float4 a = *(const float4*)(abase + i * 16 + cig * 4);
                const float* af = (const float*)&a;
                #pragma unroll
                for (int q = 0; q < 4; q++) {
                    u64 av = dup2(af[q]);
                    accC[i][0] = fma2(av, breg[q][0], accC[i][0]);
                    accC[i][1] = fma2(av, breg[q][1], accC[i][1]);
                    accC[i][2] = fma2(av, breg[q][2], accC[i][2]);
                    accC[i][3] = fma2(av, breg[q][3], accC[i][3]);
                }
            }
        }
    }
    // h = relu(conv) -> S_H as [px][64 u64]
    {
        u64* hp = (u64*)(sm + S_H);
        #pragma unroll
        for (int i = 0; i < 8; i++) {
            int p = 8 * ty + i;
            #pragma unroll
            for (int j = 0; j < 4; j++) {
                float lo, hi; unpack2(accC[i][j], lo, hi);
                hp[p * 64 + tx + 16 * j] = pack2(fmaxf(lo, 0.f), fmaxf(hi, 0.f));
            }
        }
    }

    // ============ Dense1: 128 -> 256: 8px x 8 pair-cols ============
    u64 acc1[8][8];
    {
        const u64* b1p = (const u64*)b1;
        #pragma unroll
        for (int j = 0; j < 8; j++) {
            u64 bj = __ldg(b1p + tx + 16 * j);
            #pragma unroll
            for (int i = 0; i < 8; i++) acc1[i][j] = bj;
        }
    }
    #pragma unroll
    for (int kc = 0; kc < 2; kc++) {
        __syncthreads();   // convW / previous w1 chunk dead
        {   // stage w1[kc*64 .. +64][256] = 4096 float4
            float4* s4 = (float4*)(sm + S_WA);
            const float4* g4 = (const float4*)(w1 + kc * 64 * Dch);
            #pragma unroll
            for (int u = 0; u < 16; u++) s4[tid + 256 * u] = g4[tid + 256 * u];
        }
        __syncthreads();
        const u64* h2 = (const u64*)(sm + S_H) + (8 * ty) * 64 + kc * 32;
        #pragma unroll 4
        for (int kk2 = 0; kk2 < 32; kk2++) {
            u64 alo[8], ahi[8];
            #pragma unroll
            for (int i = 0; i < 8; i++) {
                u64 a2 = h2[i * 64 + kk2];
                float lo, hi; unpack2(a2, lo, hi);
                alo[i] = dup2(lo); ahi[i] = dup2(hi);
            }
            const u64* br0 = (const u64*)(sm + S_WA) + (2 * kk2) * 128 + tx;
            const u64* br1 = br0 + 128;
            #pragma unroll
            for (int j = 0; j < 8; j++) {
                u64 bv0 = br0[16 * j];
                u64 bv1 = br1[16 * j];
                #pragma unroll
                for (int i = 0; i < 8; i++) {
                    acc1[i][j] = fma2(alo[i], bv0, acc1[i][j]);
                    acc1[i][j] = fma2(ahi[i], bv1, acc1[i][j]);
                }
            }
        }
    }
    // relu in place
    #pragma unroll
    for (int i = 0; i < 8; i++)
        #pragma unroll
        for (int j = 0; j < 8; j++) {
            float lo, hi; unpack2(acc1[i][j], lo, hi);
            acc1[i][j] = pack2(fmaxf(lo, 0.f), fmaxf(hi, 0.f));
        }

    __syncthreads();   // w1 chunk dead; S_WA becomes partial region

    // ============ Dense2 fused, FOUR c-quarters of 4 channels ============
    #pragma unroll
    for (int qd = 0; qd < 4; qd++) {
        u64 acc2[8][2];
        #pragma unroll
        for (int i = 0; i < 8; i++) { acc2[i][0] = 0ull; acc2[i][1] = 0ull; }

        #pragma unroll
        for (int j = 0; j < 8; j++) {
            const int k0 = 2 * tx + 32 * j;
            const u64* w2r0 = (const u64*)(sm + S_W2) + k0 * 9 + qd * 2;
            const u64* w2r1 = w2r0 + 9;
            u64 w00 = w2r0[0], w01 = w2r0[1];
            u64 w10 = w2r1[0], w11 = w2r1[1];
            #pragma unroll
            for (int i = 0; i < 8; i++) {
                float lo, hi; unpack2(acc1[i][j], lo, hi);
                u64 av0 = dup2(lo), av1 = dup2(hi);
                acc2[i][0] = fma2(av0, w00, acc2[i][0]);
                acc2[i][1] = fma2(av0, w01, acc2[i][1]);
                acc2[i][0] = fma2(av1, w10, acc2[i][0]);
                acc2[i][1] = fma2(av1, w11, acc2[i][1]);
            }
        }
        // write partials: part[(p*2 + cpl)*17 + tx] (u64)
        {
            u64* part = (u64*)(sm + S_WA);
            #pragma unroll
            for (int i = 0; i < 8; i++) {
                int p = 8 * ty + i;
                part[(p * 2 + 0) * 17 + tx] = acc2[i][0];
                part[(p * 2 + 1) * 17 + tx] = acc2[i][1];
            }
        }
        __syncthreads();
        // reduce: 2 outputs per thread (512 outputs per quarter)
        {
            const float* pf = sm + S_WA;
            #pragma unroll
            for (int o = 0; o < 2; o++) {
                int out = tid * 2 + o;
                int px = out >> 2, c4 = out & 3;
                int c = qd * 4 + c4;
                int cpl = c4 >> 1, comp = c4 & 1;
                int base = ((px * 2 + cpl) * 17) * 2 + comp;
                float s = 0.0f;
                #pragma unroll
                for (int g = 0; g < 16; g++) s += pf[base + 2 * g];
                int rr = px >> 6, ww = px & 63;
                const float* ctr = sm + S_IN + ((1 + rr) * 66 + ww + 1) * 16;
                float oldv = ctr[c];
                float nv = oldv;
                if (c != 0 && ctr[0] > 0.1f) nv += s + __ldg(b2 + c);
                gdst[((size_t)((b * Hdim + h0 + rr) * Wdim + ww)) * Cch + c] = nv;
            }
        }
        __syncthreads();   // before next quarter overwrites partials
    }
}

__global__ void nca_softmax(float* __restrict__ out) {
    int pix = blockIdx.x * blockDim.x + threadIdx.x;
    if (pix >= NPIX) return;
    const float* g = g_bufs[0] + (size_t)pix * Cch;
    float v[10];
    #pragma unroll
    for (int c = 0; c < 10; c++) v[c] = g[1 + c];
    float mx = v[0];
    #pragma unroll
    for (int c = 1; c < 10; c++) mx = fmaxf(mx, v[c]);
    float s = 0.0f;
    #pragma unroll
    for (int c = 0; c < 10; c++) { v[c] = __expf(v[c] - mx); s += v[c]; }
    float inv = 1.0f / s;
    float* o = out + (size_t)pix * 10;
    #pragma unroll
    for (int c = 0; c < 10; c++) o[c] = v[c] * inv;
}

extern "C" void kernel_launch(void* const* d_in, const int* in_sizes, int n_in,
                              void* d_out, int out_size) {
    const float* input = (const float*)d_in[0];
    const float* cw    = (const float*)d_in[1];
    const float* cb    = (const float*)d_in[2];
    const float* w1    = (const float*)d_in[3];
    const float* b1    = (const float*)d_in[4];
    const float* w2    = (const float*)d_in[5];
    const float* b2    = (const float*)d_in[6];

    const int smem_bytes = SMEM_FLOATS * 4;  // 174592 B
    cudaFuncSetAttribute(nca_step, cudaFuncAttributeMaxDynamicSharedMemorySize, smem_bytes);

    nca_init<<<NPIX / 256, 256>>>(input);
    for (int t = 0; t < TSTEPS; t++) {
        nca_step<<<Bdim * (Hdim / 2), 256, smem_bytes>>>(t & 1, cw, cb, w1, b1, w2, b2);
    }
    nca_softmax<<<NPIX / 256, 256>>>((float*)d_out);
}

// round 6
// speedup vs baseline: 1.9347x; 1.8838x over previous
#include <cuda_runtime.h>
#include <cuda_bf16.h>

#define Bdim 64
#define Hdim 64
#define Wdim 64
#define NPIX (Bdim * Hdim * Wdim)
#define TSTEPS 60

typedef unsigned int u32;

__device__ float g_bufs[2][NPIX * 16];

// Pre-split, pre-transposed weight images: [n][kp][2]{hi,lo};
// each u32 packs bf16(k=2kp) | bf16(k=2kp+1)<<16.
__device__ __align__(16) u32 cWt_g[128][84][2];   // conv: k=144 (72 kp) + pad
__device__ __align__(16) u32 w1t_g[256][68][2];   // d1:   k=128 (64 kp) + pad
__device__ __align__(16) u32 w2t_g[16][132][2];   // d2:   k=256 (128 kp) + pad

// split x into hi+lo bf16 pair, packed (x0 -> low 16, x1 -> high 16)
__device__ __forceinline__ void splitpk(float x0, float x1, u32& hi, u32& lo) {
    u32 h;
    asm("cvt.rn.bf16x2.f32 %0, %1, %2;" : "=r"(h) : "f"(x1), "f"(x0));
    float r0 = x0 - __uint_as_float(h << 16);
    float r1 = x1 - __uint_as_float(h & 0xFFFF0000u);
    u32 l;
    asm("cvt.rn.bf16x2.f32 %0, %1, %2;" : "=r"(l) : "f"(r1), "f"(r0));
    hi = h; lo = l;
}

__device__ __forceinline__ void mma_bf(float* c, u32 a0, u32 a1, u32 a2, u32 a3,
                                       u32 b0, u32 b1) {
    asm volatile(
        "mma.sync.aligned.m16n8k16.row.col.f32.bf16.bf16.f32 "
        "{%0,%1,%2,%3}, {%4,%5,%6,%7}, {%8,%9}, {%0,%1,%2,%3};"
        : "+f"(c[0]), "+f"(c[1]), "+f"(c[2]), "+f"(c[3])
        : "r"(a0), "r"(a1), "r"(a2), "r"(a3), "r"(b0), "r"(b1));
}

// ---------------- prep: split + transpose + pad weights (once) ----------------
__global__ void nca_prep(const float* __restrict__ cw, const float* __restrict__ w1,
                         const float* __restrict__ w2) {
    int idx = blockIdx.x * blockDim.x + threadIdx.x;
    float v0 = 0.f, v1 = 0.f;
    if (idx < 10752) {                       // cWt: 128 n x 84 kp
        int n = idx / 84, kp = idx % 84, k0 = 2 * kp;
        if (k0 < 144) {
            int tap = k0 >> 4, ci = k0 & 15;
            v0 = cw[(tap * 16 + ci) * 128 + n];
            v1 = cw[(tap * 16 + ci + 1) * 128 + n];
        }
        u32 hi, lo; splitpk(v0, v1, hi, lo);
        cWt_g[n][kp][0] = hi; cWt_g[n][kp][1] = lo;
    } else if (idx < 10752 + 17408) {        // w1t: 256 n x 68 kp
        int i = idx - 10752;
        int n = i / 68, kp = i % 68, k0 = 2 * kp;
        if (k0 < 128) { v0 = w1[k0 * 256 + n]; v1 = w1[(k0 + 1) * 256 + n]; }
        u32 hi, lo; splitpk(v0, v1, hi, lo);
        w1t_g[n][kp][0] = hi; w1t_g[n][kp][1] = lo;
    } else if (idx < 10752 + 17408 + 2112) { // w2t: 16 n x 132 kp
        int i = idx - 28160;
        int n = i / 132, kp = i % 132, k0 = 2 * kp;
        if (k0 < 256) { v0 = w2[k0 * 16 + n]; v1 = w2[(k0 + 1) * 16 + n]; }
        u32 hi, lo; splitpk(v0, v1, hi, lo);
        w2t_g[n][kp][0] = hi; w2t_g[n][kp][1] = lo;
    }
}

__global__ void nca_init(const float* __restrict__ input) {
    int pix = blockIdx.x * blockDim.x + threadIdx.x;
    if (pix < NPIX) {
        float* g = g_bufs[0] + (size_t)pix * 16;
        g[0] = input[pix];
        #pragma unroll
        for (int c = 1; c < 16; c++) g[c] = 0.0f;
    }
}

// ---------------- smem byte offsets ----------------
#define OFF_HALO 0                 // 4 x 66 x 16 fp32 = 16896 B
#define OFF_CWT  16896             // 128 x 84 x 2 u32 = 86016 B  (regionA end 102912)
#define OFF_W1C  0                 // overlay: 128 n x 68 x 2 u32 = 69632 B
#define OFF_PART 0                 // overlay: 2 x 128 x 16 fp32 = 16384 B
#define OFF_H    102912            // 128 x 68 x 2 u32 = 69632 B
#define OFF_W2   172544            // 16 x 132 x 2 u32 = 16896 B
#define SMEM_BYTES 189440

// CTA = 2 image rows (128 px). 8 warps: wm = warp&3 (32 rows), wn = warp>>2 (n half).
__global__ __launch_bounds__(256, 1) void nca_step_h(
    int sb, const float* __restrict__ cb, const float* __restrict__ b1,
    const float* __restrict__ b2)
{
    extern __shared__ unsigned char smb[];
    float* halo = (float*)(smb + OFF_HALO);
    u32*   cwt  = (u32*)(smb + OFF_CWT);
    u32*   hS   = (u32*)(smb + OFF_H);
    u32*   w1S  = (u32*)(smb + OFF_W1C);
    u32*   w2S  = (u32*)(smb + OFF_W2);
    float* part = (float*)(smb + OFF_PART);

    const float* __restrict__ gsrc = g_bufs[sb];
    float* __restrict__ gdst = g_bufs[sb ^ 1];

    const int tid  = threadIdx.x;
    const int lane = tid & 31;
    const int warp = tid >> 5;
    const int wm = warp & 3, wn = warp >> 2;
    const int qt = lane & 3, rt = lane >> 2;
    const int bI = blockIdx.x >> 5;
    const int h0 = (blockIdx.x & 31) * 2;

    // ---- stage halo (rows h0-1..h0+2, cols -1..64, zero-padded) ----
    {
        float4* s4 = (float4*)halo;
        const float4* g4 = (const float4*)gsrc;
        #pragma unroll
        for (int idx = tid; idx < 4 * 66 * 4; idx += 256) {
            int rr  = idx / (66 * 4);
            int rem = idx - rr * (66 * 4);
            int wc  = rem >> 2, c4 = rem & 3;
            int hh = h0 + rr - 1, ww = wc - 1;
            float4 v = make_float4(0.f, 0.f, 0.f, 0.f);
            if (hh >= 0 && hh < Hdim && ww >= 0 && ww < Wdim)
                v = g4[(size_t)((bI * Hdim + hh) * Wdim + ww) * 4 + c4];
            s4[idx] = v;
        }
    }
    // ---- stage conv weights + w2 ----
    {
        const uint4* s = (const uint4*)cWt_g;
        uint4* d = (uint4*)cwt;
        for (int i = tid; i < 5376; i += 256) d[i] = s[i];
        const uint4* s2 = (const uint4*)w2t_g;
        uint4* d2 = (uint4*)w2S;
        for (int i = tid; i < 1056; i += 256) d2[i] = s2[i];
    }
    __syncthreads();

    // ================= conv: M128 x N128 x K144 =================
    float acc[2][8][4];
    #pragma unroll
    for (int nt = 0; nt < 8; nt++) {
        int n0 = 8 * (8 * wn + nt) + 2 * qt;
        float bb0 = __ldg(cb + n0), bb1 = __ldg(cb + n0 + 1);
        #pragma unroll
        for (int mt = 0; mt < 2; mt++) {
            acc[mt][nt][0] = bb0; acc[mt][nt][1] = bb1;
            acc[mt][nt][2] = bb0; acc[mt][nt][3] = bb1;
        }
    }
    #pragma unroll 1
    for (int kt = 0; kt < 9; kt++) {
        const int ky = kt / 3, kx = kt - 3 * ky;
        u32 ah[2][4], al[2][4];
        #pragma unroll
        for (int mt = 0; mt < 2; mt++) {
            int p = 32 * wm + 16 * mt + rt;
            int pr = p >> 6, pw = p & 63;
            const float* cell = halo + ((pr + ky) * 66 + (pw + kx)) * 16 + 2 * qt;
            float2 v;
            v = *(const float2*)(cell);        splitpk(v.x, v.y, ah[mt][0], al[mt][0]);
            v = *(const float2*)(cell + 128);  splitpk(v.x, v.y, ah[mt][1], al[mt][1]);
            v = *(const float2*)(cell + 8);    splitpk(v.x, v.y, ah[mt][2], al[mt][2]);
            v = *(const float2*)(cell + 136);  splitpk(v.x, v.y, ah[mt][3], al[mt][3]);
        }
        #pragma unroll
        for (int nt = 0; nt < 8; nt++) {
            int n = 8 * (8 * wn + nt) + rt;
            const u32* bp = cwt + (n * 84 + 8 * kt + qt) * 2;
            uint2 B0 = *(const uint2*)bp;
            uint2 B1 = *(const uint2*)(bp + 8);
            #pragma unroll
            for (int mt = 0; mt < 2; mt++) {
                mma_bf(acc[mt][nt], ah[mt][0], ah[mt][1], ah[mt][2], ah[mt][3], B0.x, B1.x);
                mma_bf(acc[mt][nt], ah[mt][0], ah[mt][1], ah[mt][2], ah[mt][3], B0.y, B1.y);
                mma_bf(acc[mt][nt], al[mt][0], al[mt][1], al[mt][2], al[mt][3], B0.x, B1.x);
            }
        }
    }
    // h = relu(conv), split, store to H smem
    #pragma unroll
    for (int mt = 0; mt < 2; mt++) {
        int r = 32 * wm + 16 * mt + rt;
        #pragma unroll
        for (int nt = 0; nt < 8; nt++) {
            int kp = 4 * (8 * wn + nt) + qt;
            float c0 = fmaxf(acc[mt][nt][0], 0.f), c1 = fmaxf(acc[mt][nt][1], 0.f);
            float c2 = fmaxf(acc[mt][nt][2], 0.f), c3 = fmaxf(acc[mt][nt][3], 0.f);
            u32 hi01, lo01, hi23, lo23;
            splitpk(c0, c1, hi01, lo01);
            splitpk(c2, c3, hi23, lo23);
            *(uint2*)(hS + (r * 68 + kp) * 2)       = make_uint2(hi01, lo01);
            *(uint2*)(hS + ((r + 8) * 68 + kp) * 2) = make_uint2(hi23, lo23);
        }
    }
    __syncthreads();

    // ================= d1 (k=128 -> n=256) fused with d2 =================
    float acc2[2][2][4];
    #pragma unroll
    for (int mt = 0; mt < 2; mt++)
        #pragma unroll
        for (int nt = 0; nt < 2; nt++)
            #pragma unroll
            for (int e = 0; e < 4; e++) acc2[mt][nt][e] = 0.f;

    #pragma unroll 1
    for (int chunk = 0; chunk < 2; chunk++) {
        if (chunk == 1) __syncthreads();
        {   // stage w1t chunk (128 n rows)
            const uint4* s = (const uint4*)w1t_g + chunk * 4352;
            uint4* d = (uint4*)w1S;
            for (int i = tid; i < 4352; i += 256) d[i] = s[i];
        }
        __syncthreads();

        float acc1[2][8][4];
        #pragma unroll
        for (int nt = 0; nt < 8; nt++) {
            int n0 = 128 * chunk + 64 * wn + 8 * nt + 2 * qt;
            float bb0 = __ldg(b1 + n0), bb1 = __ldg(b1 + n0 + 1);
            #pragma unroll
            for (int mt = 0; mt < 2; mt++) {
                acc1[mt][nt][0] = bb0; acc1[mt][nt][1] = bb1;
                acc1[mt][nt][2] = bb0; acc1[mt][nt][3] = bb1;
            }
        }
        #pragma unroll 1
        for (int kt = 0; kt < 8; kt++) {
            u32 ah[2][4], al[2][4];
            #pragma unroll
            for (int mt = 0; mt < 2; mt++) {
                int r = 32 * wm + 16 * mt + rt;
                const u32* hp  = hS + (r * 68 + 8 * kt + qt) * 2;
                const u32* hp8 = hS + ((r + 8) * 68 + 8 * kt + qt) * 2;
                uint2 A0 = *(const uint2*)hp;
                uint2 A1 = *(const uint2*)hp8;
                uint2 A2 = *(const uint2*)(hp + 8);
                uint2 A3 = *(const uint2*)(hp8 + 8);
                ah[mt][0] = A0.x; al[mt][0] = A0.y;
                ah[mt][1] = A1.x; al[mt][1] = A1.y;
                ah[mt][2] = A2.x; al[mt][2] = A2.y;
                ah[mt][3] = A3.x; al[mt][3] = A3.y;
            }
            #pragma unroll
            for (int nt = 0; nt < 8; nt++) {
                int n = 64 * wn + 8 * nt + rt;
                const u32* bp = w1S + (n * 68 + 8 * kt + qt) * 2;
                uint2 B0 = *(const uint2*)bp;
                uint2 B1 = *(const uint2*)(bp + 8);
                #pragma unroll
                for (int mt = 0; mt < 2; mt++) {
                    mma_bf(acc1[mt][nt], ah[mt][0], ah[mt][1], ah[mt][2], ah[mt][3], B0.x, B1.x);
                    mma_bf(acc1[mt][nt], ah[mt][0], ah[mt][1], ah[mt][2], ah[mt][3], B0.y, B1.y);
                    mma_bf(acc1[mt][nt], al[mt][0], al[mt][1], al[mt][2], al[mt][3], B0.x, B1.x);
                }
            }
        }
        // a = relu(acc1) -> A-frags in regs -> d2 partial MMAs
        #pragma unroll
        for (int mt = 0; mt < 2; mt++) {
            #pragma unroll
            for (int ktl = 0; ktl < 4; ktl++) {
                float* cA = acc1[mt][2 * ktl];
                float* cB = acc1[mt][2 * ktl + 1];
                u32 ah0, al0, ah1, al1, ah2, al2, ah3, al3;
                splitpk(fmaxf(cA[0], 0.f), fmaxf(cA[1], 0.f), ah0, al0);
                splitpk(fmaxf(cA[2], 0.f), fmaxf(cA[3], 0.f), ah1, al1);
                splitpk(fmaxf(cB[0], 0.f), fmaxf(cB[1], 0.f), ah2, al2);
                splitpk(fmaxf(cB[2], 0.f), fmaxf(cB[3], 0.f), ah3, al3);
                int kpofs = 64 * chunk + 32 * wn + 8 * ktl + qt;
                #pragma unroll
                for (int nt2 = 0; nt2 < 2; nt2++) {
                    int n = 8 * nt2 + rt;
                    const u32* bp = w2S + (n * 132 + kpofs) * 2;
                    uint2 B0 = *(const uint2*)bp;
                    uint2 B1 = *(const uint2*)(bp + 8);
                    mma_bf(acc2[mt][nt2], ah0, ah1, ah2, ah3, B0.x, B1.x);
                    mma_bf(acc2[mt][nt2], ah0, ah1, ah2, ah3, B0.y, B1.y);
                    mma_bf(acc2[mt][nt2], al0, al1, al2, al3, B0.x, B1.x);
                }
            }
        }
    }
    __syncthreads();   // all w1S reads done; regionA becomes partials

    // ---- write d2 partials: part[wn][m][16] ----
    #pragma unroll
    for (int mt = 0; mt < 2; mt++) {
        int r = 32 * wm + 16 * mt + rt;
        #pragma unroll
        for (int nt2 = 0; nt2 < 2; nt2++) {
            int n0 = 8 * nt2 + 2 * qt;
            *(float2*)&part[(wn * 128 + r) * 16 + n0] =
                make_float2(acc2[mt][nt2][0], acc2[mt][nt2][1]);
            *(float2*)&part[(wn * 128 + r + 8) * 16 + n0] =
                make_float2(acc2[mt][nt2][2], acc2[mt][nt2][3]);
        }
    }
    __syncthreads();

    // ---- reduce partials + masked residual update ----
    {
        int px = tid >> 1;
        int ch0 = (tid & 1) * 8;
        int P = (bI * Hdim + h0 + (px >> 6)) * Wdim + (px & 63);
        const float* po = gsrc + (size_t)P * 16;
        float4 o0 = *(const float4*)(po + ch0);
        float4 o1 = *(const float4*)(po + ch0 + 4);
        float old[8] = {o0.x, o0.y, o0.z, o0.w, o1.x, o1.y, o1.z, o1.w};
        bool alive = po[0] > 0.1f;
        float4 pa0 = *(const float4*)&part[px * 16 + ch0];
        float4 pa1 = *(const float4*)&part[px * 16 + ch0 + 4];
        float4 pb0 = *(const float4*)&part[(128 + px) * 16 + ch0];
        float4 pb1 = *(const float4*)&part[(128 + px) * 16 + ch0 + 4];
        float d[8] = {pa0.x + pb0.x, pa0.y + pb0.y, pa0.z + pb0.z, pa0.w + pb0.w,
                      pa1.x + pb1.x, pa1.y + pb1.y, pa1.z + pb1.z, pa1.w + pb1.w};
        float out[8];
        #pragma unroll
        for (int c = 0; c < 8; c++) {
            int ch = ch0 + c;
            float nv = old[c];
            if (ch != 0 && alive) nv += d[c] + __ldg(b2 + ch);
            out[c] = nv;
        }
        float* pd = gdst + (size_t)P * 16 + ch0;
        *(float4*)pd       = make_float4(out[0], out[1], out[2], out[3]);
        *(float4*)(pd + 4) = make_float4(out[4], out[5], out[6], out[7]);
    }
}

__global__ void nca_softmax(float* __restrict__ out) {
    int pix = blockIdx.x * blockDim.x + threadIdx.x;
    if (pix >= NPIX) return;
    const float* g = g_bufs[0] + (size_t)pix * 16;
    float v[10];
    #pragma unroll
    for (int c = 0; c < 10; c++) v[c] = g[1 + c];
    float mx = v[0];
    #pragma unroll
    for (int c = 1; c < 10; c++) mx = fmaxf(mx, v[c]);
    float s = 0.0f;
    #pragma unroll
    for (int c = 0; c < 10; c++) { v[c] = __expf(v[c] - mx); s += v[c]; }
    float inv = 1.0f / s;
    float* o = out + (size_t)pix * 10;
    #pragma unroll
    for (int c = 0; c < 10; c++) o[c] = v[c] * inv;
}

extern "C" void kernel_launch(void* const* d_in, const int* in_sizes, int n_in,
                              void* d_out, int out_size) {
    const float* input = (const float*)d_in[0];
    const float* cw    = (const float*)d_in[1];
    const float* cb    = (const float*)d_in[2];
    const float* w1    = (const float*)d_in[3];
    const float* b1    = (const float*)d_in[4];
    const float* w2    = (const float*)d_in[5];
    const float* b2    = (const float*)d_in[6];

    cudaFuncSetAttribute(nca_step_h, cudaFuncAttributeMaxDynamicSharedMemorySize, SMEM_BYTES);

    nca_prep<<<119, 256>>>(cw, w1, w2);
    nca_init<<<NPIX / 256, 256>>>(input);
    for (int t = 0; t < TSTEPS; t++) {
        nca_step_h<<<Bdim * (Hdim / 2), 256, SMEM_BYTES>>>(t & 1, cb, b1, b2);
    }
    nca_softmax<<<NPIX / 256, 256>>>((float*)d_out);
}

// round 7
// speedup vs baseline: 2.5563x; 1.3213x over previous
#include <cuda_runtime.h>
#include <cuda_bf16.h>

#define Bdim 64
#define Hdim 64
#define Wdim 64
#define NPIX (Bdim * Hdim * Wdim)
#define TSTEPS 60

typedef unsigned int u32;

__device__ float g_bufs[2][NPIX * 16];

// Weight fragment images, uint4 = {B0hi, B1hi, B0lo, B1lo} (one MMA B-frag pair).
__device__ __align__(16) uint4 cW4_g[3][128][3][4];  // [stage][n][tap-in-stage][qt]
__device__ __align__(16) uint4 w14_g[4][64][9][4];   // [quarter][nl][kt(8)+pad][qt]
__device__ __align__(16) uint4 w24_g[16][16][4];     // [n][kt2][qt]

__device__ __forceinline__ void splitpk(float x0, float x1, u32& hi, u32& lo) {
    u32 h;
    asm("cvt.rn.bf16x2.f32 %0, %1, %2;" : "=r"(h) : "f"(x1), "f"(x0));
    float r0 = x0 - __uint_as_float(h << 16);
    float r1 = x1 - __uint_as_float(h & 0xFFFF0000u);
    u32 l;
    asm("cvt.rn.bf16x2.f32 %0, %1, %2;" : "=r"(l) : "f"(r1), "f"(r0));
    hi = h; lo = l;
}

__device__ __forceinline__ void mma_bf(float* c, u32 a0, u32 a1, u32 a2, u32 a3,
                                       u32 b0, u32 b1) {
    asm volatile(
        "mma.sync.aligned.m16n8k16.row.col.f32.bf16.bf16.f32 "
        "{%0,%1,%2,%3}, {%4,%5,%6,%7}, {%8,%9}, {%0,%1,%2,%3};"
        : "+f"(c[0]), "+f"(c[1]), "+f"(c[2]), "+f"(c[3])
        : "r"(a0), "r"(a1), "r"(a2), "r"(a3), "r"(b0), "r"(b1));
}

// ---------------- prep: build fragment images (once) ----------------
__global__ void nca_prep(const float* __restrict__ cw, const float* __restrict__ w1,
                         const float* __restrict__ w2) {
    int idx = blockIdx.x * blockDim.x + threadIdx.x;
    if (idx < 4608) {                         // conv: 3 g x 128 n x 3 t x 4 qt
        int g = idx / 1536, rem = idx % 1536;
        int n = rem / 12, t2 = rem % 12, t = t2 >> 2, qt = t2 & 3;
        int k0 = 16 * (3 * g + t) + 2 * qt;
        float v0 = cw[k0 * 128 + n],       v1 = cw[(k0 + 1) * 128 + n];
        float v2 = cw[(k0 + 8) * 128 + n], v3 = cw[(k0 + 9) * 128 + n];
        u32 b0h, b0l, b1h, b1l;
        splitpk(v0, v1, b0h, b0l); splitpk(v2, v3, b1h, b1l);
        cW4_g[g][n][t][qt] = make_uint4(b0h, b1h, b0l, b1l);
    } else if (idx < 13824) {                 // w1: 4 q x 64 nl x 9 kt x 4 qt
        int i = idx - 4608;
        int q = i / 2304, rem = i % 2304;
        int nl = rem / 36, r2 = rem % 36, kt = r2 >> 2, qt = r2 & 3;
        uint4 out = make_uint4(0, 0, 0, 0);
        if (kt < 8) {
            int n = 64 * q + nl, k0 = 16 * kt + 2 * qt;
            float v0 = w1[k0 * 256 + n],       v1 = w1[(k0 + 1) * 256 + n];
            float v2 = w1[(k0 + 8) * 256 + n], v3 = w1[(k0 + 9) * 256 + n];
            u32 b0h, b0l, b1h, b1l;
            splitpk(v0, v1, b0h, b0l); splitpk(v2, v3, b1h, b1l);
            out = make_uint4(b0h, b1h, b0l, b1l);
        }
        w14_g[q][nl][kt][qt] = out;
    } else if (idx < 14848) {                 // w2: 16 n x 16 kt2 x 4 qt
        int i = idx - 13824;
        int n = i / 64, r2 = i % 64, kt = r2 >> 2, qt = r2 & 3;
        int k0 = 16 * kt + 2 * qt;
        float v0 = w2[k0 * 16 + n],       v1 = w2[(k0 + 1) * 16 + n];
        float v2 = w2[(k0 + 8) * 16 + n], v3 = w2[(k0 + 9) * 16 + n];
        u32 b0h, b0l, b1h, b1l;
        splitpk(v0, v1, b0h, b0l); splitpk(v2, v3, b1h, b1l);
        w24_g[n][kt][qt] = make_uint4(b0h, b1h, b0l, b1l);
    }
}

__global__ void nca_init(const float* __restrict__ input) {
    int pix = blockIdx.x * blockDim.x + threadIdx.x;
    if (pix < NPIX) {
        float* g = g_bufs[0] + (size_t)pix * 16;
        g[0] = input[pix];
        #pragma unroll
        for (int c = 1; c < 16; c++) g[c] = 0.0f;
    }
}

// ---------------- smem byte offsets ----------------
// Region1 (0..41472): [halo 0..16896 | cw stage 16896..41472] -> [w1q 0..36864] -> [part 0..16384]
#define R1_HALO 0
#define R1_CWST 16896
#define R1_W1Q  0
#define R1_PART 0
#define OFF_HS  41472              // 128 x 68 x 2 u32 = 69632
#define SMEM_BYTES (41472 + 69632) // 111104

// CTA = 2 image rows (128 px), 8 warps (wm=warp&3, wn=warp>>2), 2 CTAs/SM.
__global__ __launch_bounds__(256, 2) void nca_step_h(
    int sb, const float* __restrict__ cb, const float* __restrict__ b1,
    const float* __restrict__ b2)
{
    extern __shared__ unsigned char smb[];
    float* halo = (float*)(smb + R1_HALO);
    uint4* cwst = (uint4*)(smb + R1_CWST);
    uint4* w1q  = (uint4*)(smb + R1_W1Q);
    u32*   hS   = (u32*)(smb + OFF_HS);
    float* part = (float*)(smb + R1_PART);

    const float* __restrict__ gsrc = g_bufs[sb];
    float* __restrict__ gdst = g_bufs[sb ^ 1];

    const int tid  = threadIdx.x;
    const int lane = tid & 31;
    const int warp = tid >> 5;
    const int wm = warp & 3, wn = warp >> 2;
    const int qt = lane & 3, rt = lane >> 2;
    const int bI = blockIdx.x >> 5;
    const int h0 = (blockIdx.x & 31) * 2;

    // ---- stage halo + conv stage 0 ----
    {
        float4* s4 = (float4*)halo;
        const float4* g4 = (const float4*)gsrc;
        #pragma unroll
        for (int idx = tid; idx < 4 * 66 * 4; idx += 256) {
            int rr  = idx / (66 * 4);
            int rem = idx - rr * (66 * 4);
            int wc  = rem >> 2, c4 = rem & 3;
            int hh = h0 + rr - 1, ww = wc - 1;
            float4 v = make_float4(0.f, 0.f, 0.f, 0.f);
            if (hh >= 0 && hh < Hdim && ww >= 0 && ww < Wdim)
                v = g4[(size_t)((bI * Hdim + hh) * Wdim + ww) * 4 + c4];
            s4[idx] = v;
        }
        const uint4* s = (const uint4*)cW4_g[0];
        #pragma unroll
        for (int i = 0; i < 6; i++) cwst[tid + 256 * i] = s[tid + 256 * i];
    }
    __syncthreads();

    // ================= conv: M128 x N128 x K144 =================
    float acc[2][8][4];
    #pragma unroll
    for (int nt = 0; nt < 8; nt++) {
        int n0 = 64 * wn + 8 * nt + 2 * qt;
        float bb0 = __ldg(cb + n0), bb1 = __ldg(cb + n0 + 1);
        #pragma unroll
        for (int mt = 0; mt < 2; mt++) {
            acc[mt][nt][0] = bb0; acc[mt][nt][1] = bb1;
            acc[mt][nt][2] = bb0; acc[mt][nt][3] = bb1;
        }
    }
    #pragma unroll 1
    for (int g = 0; g < 3; g++) {
        #pragma unroll
        for (int t = 0; t < 3; t++) {
            const int kt = 3 * g + t;
            const int ky = kt / 3, kx = kt - 3 * ky;
            u32 ah[2][4], al[2][4];
            #pragma unroll
            for (int mt = 0; mt < 2; mt++) {
                int p = 32 * wm + 16 * mt + rt;
                int pr = p >> 6, pw = p & 63;
                const float* cell = halo + ((pr + ky) * 66 + (pw + kx)) * 16 + 2 * qt;
                float2 v;
                v = *(const float2*)(cell);        splitpk(v.x, v.y, ah[mt][0], al[mt][0]);
                v = *(const float2*)(cell + 128);  splitpk(v.x, v.y, ah[mt][1], al[mt][1]);
                v = *(const float2*)(cell + 8);    splitpk(v.x, v.y, ah[mt][2], al[mt][2]);
                v = *(const float2*)(cell + 136);  splitpk(v.x, v.y, ah[mt][3], al[mt][3]);
            }
            #pragma unroll
            for (int nt = 0; nt < 8; nt++) {
                int n = 64 * wn + 8 * nt + rt;
                uint4 Bv = cwst[(n * 3 + t) * 4 + qt];
                #pragma unroll
                for (int mt = 0; mt < 2; mt++) {
                    mma_bf(acc[mt][nt], ah[mt][0], ah[mt][1], ah[mt][2], ah[mt][3], Bv.x, Bv.y);
                    mma_bf(acc[mt][nt], ah[mt][0], ah[mt][1], ah[mt][2], ah[mt][3], Bv.z, Bv.w);
                    mma_bf(acc[mt][nt], al[mt][0], al[mt][1], al[mt][2], al[mt][3], Bv.x, Bv.y);
                }
            }
        }
        if (g < 2) {
            __syncthreads();
            const uint4* s = (const uint4*)cW4_g[g + 1];
            #pragma unroll
            for (int i = 0; i < 6; i++) cwst[tid + 256 * i] = s[tid + 256 * i];
            __syncthreads();
        }
    }
    // h = relu(conv), split, store to hS
    #pragma unroll
    for (int mt = 0; mt < 2; mt++) {
        int r = 32 * wm + 16 * mt + rt;
        #pragma unroll
        for (int nt = 0; nt < 8; nt++) {
            int kp = 4 * (8 * wn + nt) + qt;
            float c0 = fmaxf(acc[mt][nt][0], 0.f), c1 = fmaxf(acc[mt][nt][1], 0.f);
            float c2 = fmaxf(acc[mt][nt][2], 0.f), c3 = fmaxf(acc[mt][nt][3], 0.f);
            u32 hi01, lo01, hi23, lo23;
            splitpk(c0, c1, hi01, lo01);
            splitpk(c2, c3, hi23, lo23);
            *(uint2*)(hS + (r * 68 + kp) * 2)       = make_uint2(hi01, lo01);
            *(uint2*)(hS + ((r + 8) * 68 + kp) * 2) = make_uint2(hi23, lo23);
        }
    }

    // ================= d1 (k=128, n in 4 quarters) fused with d2 =================
    float acc2[2][2][4];
    #pragma unroll
    for (int mt = 0; mt < 2; mt++)
        #pragma unroll
        for (int nt = 0; nt < 2; nt++)
            #pragma unroll
            for (int e = 0; e < 4; e++) acc2[mt][nt][e] = 0.f;

    #pragma unroll 1
    for (int q = 0; q < 4; q++) {
        __syncthreads();   // hS writes visible (q=0) / previous w1q reads done
        {
            const uint4* s = (const uint4*)w14_g[q];
            #pragma unroll
            for (int i = 0; i < 9; i++) w1q[tid + 256 * i] = s[tid + 256 * i];
        }
        __syncthreads();

        float acc1[2][4][4];
        #pragma unroll
        for (int nt = 0; nt < 4; nt++) {
            int n0 = 64 * q + 32 * wn + 8 * nt + 2 * qt;
            float bb0 = __ldg(b1 + n0), bb1 = __ldg(b1 + n0 + 1);
            #pragma unroll
            for (int mt = 0; mt < 2; mt++) {
                acc1[mt][nt][0] = bb0; acc1[mt][nt][1] = bb1;
                acc1[mt][nt][2] = bb0; acc1[mt][nt][3] = bb1;
            }
        }
        #pragma unroll 1
        for (int kt = 0; kt < 8; kt++) {
            u32 ah[2][4], al[2][4];
            #pragma unroll
            for (int mt = 0; mt < 2; mt++) {
                int r = 32 * wm + 16 * mt + rt;
                const u32* hp  = hS + (r * 68 + 8 * kt + qt) * 2;
                const u32* hp8 = hS + ((r + 8) * 68 + 8 * kt + qt) * 2;
                uint2 A0 = *(const uint2*)hp;
                uint2 A1 = *(const uint2*)hp8;
                uint2 A2 = *(const uint2*)(hp + 8);
                uint2 A3 = *(const uint2*)(hp8 + 8);
                ah[mt][0] = A0.x; al[mt][0] = A0.y;
                ah[mt][1] = A1.x; al[mt][1] = A1.y;
                ah[mt][2] = A2.x; al[mt][2] = A2.y;
                ah[mt][3] = A3.x; al[mt][3] = A3.y;
            }
            #pragma unroll
            for (int nt = 0; nt < 4; nt++) {
                int nl = 32 * wn + 8 * nt + rt;
                uint4 Bv = w1q[(nl * 9 + kt) * 4 + qt];
                #pragma unroll
                for (int mt = 0; mt < 2; mt++) {
                    mma_bf(acc1[mt][nt], ah[mt][0], ah[mt][1], ah[mt][2], ah[mt][3], Bv.x, Bv.y);
                    mma_bf(acc1[mt][nt], ah[mt][0], ah[mt][1], ah[mt][2], ah[mt][3], Bv.z, Bv.w);
                    mma_bf(acc1[mt][nt], al[mt][0], al[mt][1], al[mt][2], al[mt][3], Bv.x, Bv.y);
                }
            }
        }
        // a = relu(acc1) -> register A-frags -> d2 partial MMAs
        #pragma unroll
        for (int mt = 0; mt < 2; mt++) {
            #pragma unroll
            for (int ktl = 0; ktl < 2; ktl++) {
                float* cA = acc1[mt][2 * ktl];
                float* cB = acc1[mt][2 * ktl + 1];
                u32 ah0, al0, ah1, al1, ah2, al2, ah3, al3;
                splitpk(fmaxf(cA[0], 0.f), fmaxf(cA[1], 0.f), ah0, al0);
                splitpk(fmaxf(cA[2], 0.f), fmaxf(cA[3], 0.f), ah1, al1);
                splitpk(fmaxf(cB[0], 0.f), fmaxf(cB[1], 0.f), ah2, al2);
                splitpk(fmaxf(cB[2], 0.f), fmaxf(cB[3], 0.f), ah3, al3);
                int kt2 = 4 * q + 2 * wn + ktl;
                #pragma unroll
                for (int nt2 = 0; nt2 < 2; nt2++) {
                    uint4 Bv = __ldg(&w24_g[8 * nt2 + rt][kt2][qt]);
                    mma_bf(acc2[mt][nt2], ah0, ah1, ah2, ah3, Bv.x, Bv.y);
                    mma_bf(acc2[mt][nt2], ah0, ah1, ah2, ah3, Bv.z, Bv.w);
                    mma_bf(acc2[mt][nt2], al0, al1, al2, al3, Bv.x, Bv.y);
                }
            }
        }
    }
    __syncthreads();   // last w1q reads done; region1 becomes partials

    // ---- write d2 partials: part[wn][m][16] ----
    #pragma unroll
    for (int mt = 0; mt < 2; mt++) {
        int r = 32 * wm + 16 * mt + rt;
        #pragma unroll
        for (int nt2 = 0; nt2 < 2; nt2++) {
            int n0 = 8 * nt2 + 2 * qt;
            *(float2*)&part[(wn * 128 + r) * 16 + n0] =
                make_float2(acc2[mt][nt2][0], acc2[mt][nt2][1]);
            *(float2*)&part[(wn * 128 + r + 8) * 16 + n0] =
                make_float2(acc2[mt][nt2][2], acc2[mt][nt2][3]);
        }
    }
    __syncthreads();

    // ---- reduce partials + masked residual update ----
    {
        int px = tid >> 1;
        int ch0 = (tid & 1) * 8;
        int P = (bI * Hdim + h0 + (px >> 6)) * Wdim + (px & 63);
        const float* po = gsrc + (size_t)P * 16;
        float4 o0 = *(const float4*)(po + ch0);
        float4 o1 = *(const float4*)(po + ch0 + 4);
        float old[8] = {o0.x, o0.y, o0.z, o0.w, o1.x, o1.y, o1.z, o1.w};
        bool alive = po[0] > 0.1f;
        float4 pa0 = *(const float4*)&part[px * 16 + ch0];
        float4 pa1 = *(const float4*)&part[px * 16 + ch0 + 4];
        float4 pb0 = *(const float4*)&part[(128 + px) * 16 + ch0];
        float4 pb1 = *(const float4*)&part[(128 + px) * 16 + ch0 + 4];
        float d[8] = {pa0.x + pb0.x, pa0.y + pb0.y, pa0.z + pb0.z, pa0.w + pb0.w,
                      pa1.x + pb1.x, pa1.y + pb1.y, pa1.z + pb1.z, pa1.w + pb1.w};
        float out[8];
        #pragma unroll
        for (int c = 0; c < 8; c++) {
            int ch = ch0 + c;
            float nv = old[c];
            if (ch != 0 && alive) nv += d[c] + __ldg(b2 + ch);
            out[c] = nv;
        }
        float* pd = gdst + (size_t)P * 16 + ch0;
        *(float4*)pd       = make_float4(out[0], out[1], out[2], out[3]);
        *(float4*)(pd + 4) = make_float4(out[4], out[5], out[6], out[7]);
    }
}

__global__ void nca_softmax(float* __restrict__ out) {
    int pix = blockIdx.x * blockDim.x + threadIdx.x;
    if (pix >= NPIX) return;
    const float* g = g_bufs[0] + (size_t)pix * 16;
    float v[10];
    #pragma unroll
    for (int c = 0; c < 10; c++) v[c] = g[1 + c];
    float mx = v[0];
    #pragma unroll
    for (int c = 1; c < 10; c++) mx = fmaxf(mx, v[c]);
    float s = 0.0f;
    #pragma unroll
    for (int c = 0; c < 10; c++) { v[c] = __expf(v[c] - mx); s += v[c]; }
    float inv = 1.0f / s;
    float* o = out + (size_t)pix * 10;
    #pragma unroll
    for (int c = 0; c < 10; c++) o[c] = v[c] * inv;
}

extern "C" void kernel_launch(void* const* d_in, const int* in_sizes, int n_in,
                              void* d_out, int out_size) {
    const float* input = (const float*)d_in[0];
    const float* cw    = (const float*)d_in[1];
    const float* cb    = (const float*)d_in[2];
    const float* w1    = (const float*)d_in[3];
    const float* b1    = (const float*)d_in[4];
    const float* w2    = (const float*)d_in[5];
    const float* b2    = (const float*)d_in[6];

    cudaFuncSetAttribute(nca_step_h, cudaFuncAttributeMaxDynamicSharedMemorySize, SMEM_BYTES);

    nca_prep<<<58, 256>>>(cw, w1, w2);
    nca_init<<<NPIX / 256, 256>>>(input);
    for (int t = 0; t < TSTEPS; t++) {
        nca_step_h<<<Bdim * (Hdim / 2), 256, SMEM_BYTES>>>(t & 1, cb, b1, b2);
    }
    nca_softmax<<<NPIX / 256, 256>>>((float*)d_out);
}

// round 8
// speedup vs baseline: 2.5786x; 1.0087x over previous
#include <cuda_runtime.h>
#include <cuda_bf16.h>

#define Bdim 64
#define Hdim 64
#define Wdim 64
#define NPIX (Bdim * Hdim * Wdim)
#define TSTEPS 60

typedef unsigned int u32;

__device__ float g_bufs[2][NPIX * 16];

// Weight fragment images, uint4 = {B0hi, B1hi, B0lo, B1lo} (one MMA B-frag pair).
// Laid out so one warp's fragment fetch is a contiguous 512B stripe.
__device__ __align__(16) uint4 cW4_g[9][128][4];     // [tap][n][qt]
__device__ __align__(16) uint4 w14_g[4][8][64][4];   // [quarter][kt][nl][qt]
__device__ __align__(16) uint4 w24_g[16][16][4];     // [n][kt2][qt]

__device__ __forceinline__ void splitpk(float x0, float x1, u32& hi, u32& lo) {
    u32 h;
    asm("cvt.rn.bf16x2.f32 %0, %1, %2;" : "=r"(h) : "f"(x1), "f"(x0));
    float r0 = x0 - __uint_as_float(h << 16);
    float r1 = x1 - __uint_as_float(h & 0xFFFF0000u);
    u32 l;
    asm("cvt.rn.bf16x2.f32 %0, %1, %2;" : "=r"(l) : "f"(r1), "f"(r0));
    hi = h; lo = l;
}

__device__ __forceinline__ void mma_bf(float* c, u32 a0, u32 a1, u32 a2, u32 a3,
                                       u32 b0, u32 b1) {
    asm volatile(
        "mma.sync.aligned.m16n8k16.row.col.f32.bf16.bf16.f32 "
        "{%0,%1,%2,%3}, {%4,%5,%6,%7}, {%8,%9}, {%0,%1,%2,%3};"
        : "+f"(c[0]), "+f"(c[1]), "+f"(c[2]), "+f"(c[3])
        : "r"(a0), "r"(a1), "r"(a2), "r"(a3), "r"(b0), "r"(b1));
}

// ---------------- prep: build fragment images (once) ----------------
__global__ void nca_prep(const float* __restrict__ cw, const float* __restrict__ w1,
                         const float* __restrict__ w2) {
    int idx = blockIdx.x * blockDim.x + threadIdx.x;
    if (idx < 4608) {                         // conv: 9 tap x 128 n x 4 qt
        int tap = idx >> 9, rem = idx & 511;
        int n = rem >> 2, qt = rem & 3;
        int k0 = 16 * tap + 2 * qt;
        float v0 = cw[k0 * 128 + n],       v1 = cw[(k0 + 1) * 128 + n];
        float v2 = cw[(k0 + 8) * 128 + n], v3 = cw[(k0 + 9) * 128 + n];
        u32 b0h, b0l, b1h, b1l;
        splitpk(v0, v1, b0h, b0l); splitpk(v2, v3, b1h, b1l);
        cW4_g[tap][n][qt] = make_uint4(b0h, b1h, b0l, b1l);
    } else if (idx < 4608 + 8192) {           // w1: 4 q x 8 kt x 64 nl x 4 qt
        int i = idx - 4608;
        int q = i >> 11, rem = i & 2047;
        int kt = rem >> 8, r2 = rem & 255, nl = r2 >> 2, qt = r2 & 3;
        int n = 64 * q + nl, k0 = 16 * kt + 2 * qt;
        float v0 = w1[k0 * 256 + n],       v1 = w1[(k0 + 1) * 256 + n];
        float v2 = w1[(k0 + 8) * 256 + n], v3 = w1[(k0 + 9) * 256 + n];
        u32 b0h, b0l, b1h, b1l;
        splitpk(v0, v1, b0h, b0l); splitpk(v2, v3, b1h, b1l);
        w14_g[q][kt][nl][qt] = make_uint4(b0h, b1h, b0l, b1l);
    } else if (idx < 4608 + 8192 + 1024) {    // w2: 16 n x 16 kt2 x 4 qt
        int i = idx - 12800;
        int n = i >> 6, r2 = i & 63, kt = r2 >> 2, qt = r2 & 3;
        int k0 = 16 * kt + 2 * qt;
        float v0 = w2[k0 * 16 + n],       v1 = w2[(k0 + 1) * 16 + n];
        float v2 = w2[(k0 + 8) * 16 + n], v3 = w2[(k0 + 9) * 16 + n];
        u32 b0h, b0l, b1h, b1l;
        splitpk(v0, v1, b0h, b0l); splitpk(v2, v3, b1h, b1l);
        w24_g[n][kt][qt] = make_uint4(b0h, b1h, b0l, b1l);
    }
}

__global__ void nca_init(const float* __restrict__ input) {
    int pix = blockIdx.x * blockDim.x + threadIdx.x;
    if (pix < NPIX) {
        float* g = g_bufs[0] + (size_t)pix * 16;
        g[0] = input[pix];
        #pragma unroll
        for (int c = 1; c < 16; c++) g[c] = 0.0f;
    }
}

// ---------------- smem layout ----------------
// haloS: 264 cells x 8 q8 x uint2{hi,lo} = 16896 B   (overlaid by partials later)
// hS:    128 x 68 x 2 u32 = 69632 B
#define R_HALOS 0
#define R_PART  0
#define OFF_HS  16896
#define SMEM_BYTES (16896 + 69632)   // 86528

// CTA = 2 image rows (128 px), 8 warps (wm=warp&3, wn=warp>>2), 2 CTAs/SM.
__global__ __launch_bounds__(256, 2) void nca_step_h(
    int sb, const float* __restrict__ cb, const float* __restrict__ b1,
    const float* __restrict__ b2)
{
    extern __shared__ unsigned char smb[];
    uint2* haloS = (uint2*)(smb + R_HALOS);
    u32*   hS    = (u32*)(smb + OFF_HS);
    float* part  = (float*)(smb + R_PART);

    const float* __restrict__ gsrc = g_bufs[sb];
    float* __restrict__ gdst = g_bufs[sb ^ 1];

    const int tid  = threadIdx.x;
    const int lane = tid & 31;
    const int warp = tid >> 5;
    const int wm = warp & 3, wn = warp >> 2;
    const int qt = lane & 3, rt = lane >> 2;
    const int bI = blockIdx.x >> 5;
    const int h0 = (blockIdx.x & 31) * 2;

    // ---- cooperative halo pre-split: cell = rr*66+wc, q8 = channel-pair ----
    #pragma unroll
    for (int idx = tid; idx < 2112; idx += 256) {
        int cell = idx >> 3, q8 = idx & 7;
        int rr = cell / 66, wc = cell - rr * 66;
        int hh = h0 + rr - 1, ww = wc - 1;
        float2 v = make_float2(0.f, 0.f);
        if (hh >= 0 && hh < Hdim && ww >= 0 && ww < Wdim)
            v = *(const float2*)(gsrc + ((size_t)((bI * Hdim + hh) * Wdim + ww) << 4) + 2 * q8);
        u32 hi, lo; splitpk(v.x, v.y, hi, lo);
        haloS[idx] = make_uint2(hi, lo);
    }
    __syncthreads();

    // ================= conv: M128 x N128 x K144 =================
    float acc[2][8][4];
    #pragma unroll
    for (int nt = 0; nt < 8; nt++) {
        int n0 = 64 * wn + 8 * nt + 2 * qt;
        float bb0 = __ldg(cb + n0), bb1 = __ldg(cb + n0 + 1);
        #pragma unroll
        for (int mt = 0; mt < 2; mt++) {
            acc[mt][nt][0] = bb0; acc[mt][nt][1] = bb1;
            acc[mt][nt][2] = bb0; acc[mt][nt][3] = bb1;
        }
    }
    #pragma unroll 1
    for (int tap = 0; tap < 9; tap++) {
        const int ky = tap / 3, kx = tap - 3 * ky;
        u32 ah[2][4], al[2][4];
        #pragma unroll
        for (int mt = 0; mt < 2; mt++) {
            int p  = 32 * wm + 16 * mt + rt;
            int p8 = p + 8;
            int c0 = ((p >> 6) + ky) * 66 + (p & 63) + kx;
            int c1 = ((p8 >> 6) + ky) * 66 + (p8 & 63) + kx;
            uint2 A0 = haloS[c0 * 8 + qt];
            uint2 A1 = haloS[c1 * 8 + qt];
            uint2 A2 = haloS[c0 * 8 + qt + 4];
            uint2 A3 = haloS[c1 * 8 + qt + 4];
            ah[mt][0] = A0.x; al[mt][0] = A0.y;
            ah[mt][1] = A1.x; al[mt][1] = A1.y;
            ah[mt][2] = A2.x; al[mt][2] = A2.y;
            ah[mt][3] = A3.x; al[mt][3] = A3.y;
        }
        #pragma unroll
        for (int nt = 0; nt < 8; nt++) {
            uint4 Bv = __ldg(&cW4_g[tap][64 * wn + 8 * nt + rt][qt]);
            #pragma unroll
            for (int mt = 0; mt < 2; mt++) {
                mma_bf(acc[mt][nt], ah[mt][0], ah[mt][1], ah[mt][2], ah[mt][3], Bv.x, Bv.y);
                mma_bf(acc[mt][nt], ah[mt][0], ah[mt][1], ah[mt][2], ah[mt][3], Bv.z, Bv.w);
                mma_bf(acc[mt][nt], al[mt][0], al[mt][1], al[mt][2], al[mt][3], Bv.x, Bv.y);
            }
        }
    }
    // h = relu(conv), split, store to hS
    #pragma unroll
    for (int mt = 0; mt < 2; mt++) {
        int r = 32 * wm + 16 * mt + rt;
        #pragma unroll
        for (int nt = 0; nt < 8; nt++) {
            int kp = 4 * (8 * wn + nt) + qt;
            float c0 = fmaxf(acc[mt][nt][0], 0.f), c1 = fmaxf(acc[mt][nt][1], 0.f);
            float c2 = fmaxf(acc[mt][nt][2], 0.f), c3 = fmaxf(acc[mt][nt][3], 0.f);
            u32 hi01, lo01, hi23, lo23;
            splitpk(c0, c1, hi01, lo01);
            splitpk(c2, c3, hi23, lo23);
            *(uint2*)(hS + (r * 68 + kp) * 2)       = make_uint2(hi01, lo01);
            *(uint2*)(hS + ((r + 8) * 68 + kp) * 2) = make_uint2(hi23, lo23);
        }
    }
    __syncthreads();   // hS complete; haloS reads done (partials may overlay)

    // ================= d1 (k=128, n in 4 quarters) fused with d2 =================
    float acc2[2][2][4];
    #pragma unroll
    for (int mt = 0; mt < 2; mt++)
        #pragma unroll
        for (int nt = 0; nt < 2; nt++)
            #pragma unroll
            for (int e = 0; e < 4; e++) acc2[mt][nt][e] = 0.f;

    #pragma unroll 1
    for (int q = 0; q < 4; q++) {
        float acc1[2][4][4];
        #pragma unroll
        for (int nt = 0; nt < 4; nt++) {
            int n0 = 64 * q + 32 * wn + 8 * nt + 2 * qt;
            float bb0 = __ldg(b1 + n0), bb1 = __ldg(b1 + n0 + 1);
            #pragma unroll
            for (int mt = 0; mt < 2; mt++) {
                acc1[mt][nt][0] = bb0; acc1[mt][nt][1] = bb1;
                acc1[mt][nt][2] = bb0; acc1[mt][nt][3] = bb1;
            }
        }
        #pragma unroll 2
        for (int kt = 0; kt < 8; kt++) {
            u32 ah[2][4], al[2][4];
            #pragma unroll
            for (int mt = 0; mt < 2; mt++) {
                int r = 32 * wm + 16 * mt + rt;
                const u32* hp  = hS + (r * 68 + 8 * kt + qt) * 2;
                const u32* hp8 = hS + ((r + 8) * 68 + 8 * kt + qt) * 2;
                uint2 A0 = *(const uint2*)hp;
                uint2 A1 = *(const uint2*)hp8;
                uint2 A2 = *(const uint2*)(hp + 8);
                uint2 A3 = *(const uint2*)(hp8 + 8);
                ah[mt][0] = A0.x; al[mt][0] = A0.y;
                ah[mt][1] = A1.x; al[mt][1] = A1.y;
                ah[mt][2] = A2.x; al[mt][2] = A2.y;
                ah[mt][3] = A3.x; al[mt][3] = A3.y;
            }
            #pragma unroll
            for (int nt = 0; nt < 4; nt++) {
                uint4 Bv = __ldg(&w14_g[q][kt][32 * wn + 8 * nt + rt][qt]);
                #pragma unroll
                for (int mt = 0; mt < 2; mt++) {
                    mma_bf(acc1[mt][nt], ah[mt][0], ah[mt][1], ah[mt][2], ah[mt][3], Bv.x, Bv.y);
                    mma_bf(acc1[mt][nt], ah[mt][0], ah[mt][1], ah[mt][2], ah[mt][3], Bv.z, Bv.w);
                    mma_bf(acc1[mt][nt], al[mt][0], al[mt][1], al[mt][2], al[mt][3], Bv.x, Bv.y);
                }
            }
        }
        // a = relu(acc1) -> register A-frags -> d2 partial MMAs
        #pragma unroll
        for (int mt = 0; mt < 2; mt++) {
            #pragma unroll
            for (int ktl = 0; ktl < 2; ktl++) {
                float* cA = acc1[mt][2 * ktl];
                float* cB = acc1[mt][2 * ktl + 1];
                u32 ah0, al0, ah1, al1, ah2, al2, ah3, al3;
                splitpk(fmaxf(cA[0], 0.f), fmaxf(cA[1], 0.f), ah0, al0);
                splitpk(fmaxf(cA[2], 0.f), fmaxf(cA[3], 0.f), ah1, al1);
                splitpk(fmaxf(cB[0], 0.f), fmaxf(cB[1], 0.f), ah2, al2);
                splitpk(fmaxf(cB[2], 0.f), fmaxf(cB[3], 0.f), ah3, al3);
                int kt2 = 4 * q + 2 * wn + ktl;
                #pragma unroll
                for (int nt2 = 0; nt2 < 2; nt2++) {
                    uint4 Bv = __ldg(&w24_g[8 * nt2 + rt][kt2][qt]);
                    mma_bf(acc2[mt][nt2], ah0, ah1, ah2, ah3, Bv.x, Bv.y);
                    mma_bf(acc2[mt][nt2], ah0, ah1, ah2, ah3, Bv.z, Bv.w);
                    mma_bf(acc2[mt][nt2], al0, al1, al2, al3, Bv.x, Bv.y);
                }
            }
        }
    }

    // ---- write d2 partials: part[wn][m][16] (overlays haloS; safe post-sync) ----
    #pragma unroll
    for (int mt = 0; mt < 2; mt++) {
        int r = 32 * wm + 16 * mt + rt;
        #pragma unroll
        for (int nt2 = 0; nt2 < 2; nt2++) {
            int n0 = 8 * nt2 + 2 * qt;
            *(float2*)&part[(wn * 128 + r) * 16 + n0] =
                make_float2(acc2[mt][nt2][0], acc2[mt][nt2][1]);
            *(float2*)&part[(wn * 128 + r + 8) * 16 + n0] =
                make_float2(acc2[mt][nt2][2], acc2[mt][nt2][3]);
        }
    }
    __syncthreads();

    // ---- reduce partials + masked residual update ----
    {
        int px = tid >> 1;
        int ch0 = (tid & 1) * 8;
        int P = (bI * Hdim + h0 + (px >> 6)) * Wdim + (px & 63);
        const float* po = gsrc + (size_t)P * 16;
        float4 o0 = *(const float4*)(po + ch0);
        float4 o1 = *(const float4*)(po + ch0 + 4);
        float old[8] = {o0.x, o0.y, o0.z, o0.w, o1.x, o1.y, o1.z, o1.w};
        bool alive = po[0] > 0.1f;
        float4 pa0 = *(const float4*)&part[px * 16 + ch0];
        float4 pa1 = *(const float4*)&part[px * 16 + ch0 + 4];
        float4 pb0 = *(const float4*)&part[(128 + px) * 16 + ch0];
        float4 pb1 = *(const float4*)&part[(128 + px) * 16 + ch0 + 4];
        float d[8] = {pa0.x + pb0.x, pa0.y + pb0.y, pa0.z + pb0.z, pa0.w + pb0.w,
                      pa1.x + pb1.x, pa1.y + pb1.y, pa1.z + pb1.z, pa1.w + pb1.w};
        float out[8];
        #pragma unroll
        for (int c = 0; c < 8; c++) {
            int ch = ch0 + c;
            float nv = old[c];
            if (ch != 0 && alive) nv += d[c] + __ldg(b2 + ch);
            out[c] = nv;
        }
        float* pd = gdst + (size_t)P * 16 + ch0;
        *(float4*)pd       = make_float4(out[0], out[1], out[2], out[3]);
        *(float4*)(pd + 4) = make_float4(out[4], out[5], out[6], out[7]);
    }
}

__global__ void nca_softmax(float* __restrict__ out) {
    int pix = blockIdx.x * blockDim.x + threadIdx.x;
    if (pix >= NPIX) return;
    const float* g = g_bufs[0] + (size_t)pix * 16;
    float v[10];
    #pragma unroll
    for (int c = 0; c < 10; c++) v[c] = g[1 + c];
    float mx = v[0];
    #pragma unroll
    for (int c = 1; c < 10; c++) mx = fmaxf(mx, v[c]);
    float s = 0.0f;
    #pragma unroll
    for (int c = 0; c < 10; c++) { v[c] = __expf(v[c] - mx); s += v[c]; }
    float inv = 1.0f / s;
    float* o = out + (size_t)pix * 10;
    #pragma unroll
    for (int c = 0; c < 10; c++) o[c] = v[c] * inv;
}

extern "C" void kernel_launch(void* const* d_in, const int* in_sizes, int n_in,
                              void* d_out, int out_size) {
    const float* input = (const float*)d_in[0];
    const float* cw    = (const float*)d_in[1];
    const float* cb    = (const float*)d_in[2];
    const float* w1    = (const float*)d_in[3];
    const float* b1    = (const float*)d_in[4];
    const float* w2    = (const float*)d_in[5];
    const float* b2    = (const float*)d_in[6];

    cudaFuncSetAttribute(nca_step_h, cudaFuncAttributeMaxDynamicSharedMemorySize, SMEM_BYTES);

    nca_prep<<<54, 256>>>(cw, w1, w2);
    nca_init<<<NPIX / 256, 256>>>(input);
    for (int t = 0; t < TSTEPS; t++) {
        nca_step_h<<<Bdim * (Hdim / 2), 256, SMEM_BYTES>>>(t & 1, cb, b1, b2);
    }
    nca_softmax<<<NPIX / 256, 256>>>((float*)d_out);
}

// round 9
// speedup vs baseline: 2.7628x; 1.0714x over previous
#include <cuda_runtime.h>
#include <cuda_bf16.h>

#define Bdim 64
#define Hdim 64
#define Wdim 64
#define NPIX (Bdim * Hdim * Wdim)
#define TSTEPS 60

typedef unsigned int u32;

__device__ float g_bufs[2][NPIX * 16];

// Weight fragment images, uint4 = {B0hi, B1hi, B0lo, B1lo} (one MMA B-frag pair).
__device__ __align__(16) uint4 cW4_g[9][128][4];     // [tap][n][qt]
__device__ __align__(16) uint4 w14_g[4][8][64][4];   // [quarter][kt][nl][qt]
__device__ __align__(16) uint4 w24_g[16][16][4];     // [n][kt2][qt]

__device__ __forceinline__ void splitpk(float x0, float x1, u32& hi, u32& lo) {
    u32 h;
    asm("cvt.rn.bf16x2.f32 %0, %1, %2;" : "=r"(h) : "f"(x1), "f"(x0));
    float r0 = x0 - __uint_as_float(h << 16);
    float r1 = x1 - __uint_as_float(h & 0xFFFF0000u);
    u32 l;
    asm("cvt.rn.bf16x2.f32 %0, %1, %2;" : "=r"(l) : "f"(r1), "f"(r0));
    hi = h; lo = l;
}

__device__ __forceinline__ void mma_bf(float* c, u32 a0, u32 a1, u32 a2, u32 a3,
                                       u32 b0, u32 b1) {
    asm volatile(
        "mma.sync.aligned.m16n8k16.row.col.f32.bf16.bf16.f32 "
        "{%0,%1,%2,%3}, {%4,%5,%6,%7}, {%8,%9}, {%0,%1,%2,%3};"
        : "+f"(c[0]), "+f"(c[1]), "+f"(c[2]), "+f"(c[3])
        : "r"(a0), "r"(a1), "r"(a2), "r"(a3), "r"(b0), "r"(b1));
}

// ---------------- prep: build fragment images (once) ----------------
__global__ void nca_prep(const float* __restrict__ cw, const float* __restrict__ w1,
                         const float* __restrict__ w2) {
    int idx = blockIdx.x * blockDim.x + threadIdx.x;
    if (idx < 4608) {                         // conv: 9 tap x 128 n x 4 qt
        int tap = idx >> 9, rem = idx & 511;
        int n = rem >> 2, qt = rem & 3;
        int k0 = 16 * tap + 2 * qt;
        float v0 = cw[k0 * 128 + n],       v1 = cw[(k0 + 1) * 128 + n];
        float v2 = cw[(k0 + 8) * 128 + n], v3 = cw[(k0 + 9) * 128 + n];
        u32 b0h, b0l, b1h, b1l;
        splitpk(v0, v1, b0h, b0l); splitpk(v2, v3, b1h, b1l);
        cW4_g[tap][n][qt] = make_uint4(b0h, b1h, b0l, b1l);
    } else if (idx < 4608 + 8192) {           // w1: 4 q x 8 kt x 64 nl x 4 qt
        int i = idx - 4608;
        int q = i >> 11, rem = i & 2047;
        int kt = rem >> 8, r2 = rem & 255, nl = r2 >> 2, qt = r2 & 3;
        int n = 64 * q + nl, k0 = 16 * kt + 2 * qt;
        float v0 = w1[k0 * 256 + n],       v1 = w1[(k0 + 1) * 256 + n];
        float v2 = w1[(k0 + 8) * 256 + n], v3 = w1[(k0 + 9) * 256 + n];
        u32 b0h, b0l, b1h, b1l;
        splitpk(v0, v1, b0h, b0l); splitpk(v2, v3, b1h, b1l);
        w14_g[q][kt][nl][qt] = make_uint4(b0h, b1h, b0l, b1l);
    } else if (idx < 4608 + 8192 + 1024) {    // w2: 16 n x 16 kt2 x 4 qt
        int i = idx - 12800;
        int n = i >> 6, r2 = i & 63, kt = r2 >> 2, qt = r2 & 3;
        int k0 = 16 * kt + 2 * qt;
        float v0 = w2[k0 * 16 + n],       v1 = w2[(k0 + 1) * 16 + n];
        float v2 = w2[(k0 + 8) * 16 + n], v3 = w2[(k0 + 9) * 16 + n];
        u32 b0h, b0l, b1h, b1l;
        splitpk(v0, v1, b0h, b0l); splitpk(v2, v3, b1h, b1l);
        w24_g[n][kt][qt] = make_uint4(b0h, b1h, b0l, b1l);
    }
}

__global__ void nca_init(const float* __restrict__ input) {
    int pix = blockIdx.x * blockDim.x + threadIdx.x;
    if (pix < NPIX) {
        float* g = g_bufs[0] + (size_t)pix * 16;
        g[0] = input[pix];
        #pragma unroll
        for (int c = 1; c < 16; c++) g[c] = 0.0f;
    }
}

// ---------------- smem layout ----------------
// region0 [0,16384): haloS (3x66 cells x 8 q8 x uint2 = 12672 B) -> partials (16384 B)
// hS at 16384: 64 rows x 68 kp x uint2 = 34816 B
#define R_HALOS 0
#define R_PART  0
#define OFF_HS  16384
#define SMEM_BYTES (16384 + 34816)   // 51200

// CTA = 1 image row (64 px), 8 warps: wm = warp&1 (m half), wn = warp>>1 (n 4-way).
__global__ __launch_bounds__(256, 3) void nca_step_h(
    int sb, const float* __restrict__ cb, const float* __restrict__ b1,
    const float* __restrict__ b2)
{
    extern __shared__ unsigned char smb[];
    uint2* haloS = (uint2*)(smb + R_HALOS);
    u32*   hS    = (u32*)(smb + OFF_HS);
    float* part  = (float*)(smb + R_PART);

    const float* __restrict__ gsrc = g_bufs[sb];
    float* __restrict__ gdst = g_bufs[sb ^ 1];

    const int tid  = threadIdx.x;
    const int lane = tid & 31;
    const int warp = tid >> 5;
    const int wm = warp & 1, wn = warp >> 1;
    const int qt = lane & 3, rt = lane >> 2;
    const int bI = blockIdx.x >> 6;
    const int h0 = blockIdx.x & 63;

    // ---- cooperative halo pre-split: 3 rows (h0-1..h0+1) x 66 cells x 8 q8 ----
    #pragma unroll
    for (int idx = tid; idx < 1584; idx += 256) {
        int cell = idx >> 3, q8 = idx & 7;
        int rr = cell / 66, wc = cell - rr * 66;
        int hh = h0 + rr - 1, ww = wc - 1;
        float2 v = make_float2(0.f, 0.f);
        if (hh >= 0 && hh < Hdim && ww >= 0 && ww < Wdim)
            v = *(const float2*)(gsrc + ((size_t)((bI * Hdim + hh) * Wdim + ww) << 4) + 2 * q8);
        u32 hi, lo; splitpk(v.x, v.y, hi, lo);
        haloS[idx] = make_uint2(hi, lo);
    }
    __syncthreads();

    // hoisted per-warp fragment pointers
    const uint4* cwB = &cW4_g[0][32 * wn + rt][qt];          // +tap*512 +nt*32
    const uint4* w1B = &w14_g[0][0][16 * wn + rt][qt];       // +q*2048 +kt*256 +nt*32
    const uint4* w2B = (const uint4*)w24_g + rt * 64 + wn * 4 + qt;  // +nt2*512 +q*16
    const u32*   hA  = hS + (32 * wm + rt) * 136 + qt * 2;   // +mt*2176 +kt*16 (+8 k, +1088 r+8)

    // ================= conv: M64 x N128 x K144 =================
    float acc[2][4][4];
    #pragma unroll
    for (int nt = 0; nt < 4; nt++) {
        int n0 = 32 * wn + 8 * nt + 2 * qt;
        float bb0 = __ldg(cb + n0), bb1 = __ldg(cb + n0 + 1);
        #pragma unroll
        for (int mt = 0; mt < 2; mt++) {
            acc[mt][nt][0] = bb0; acc[mt][nt][1] = bb1;
            acc[mt][nt][2] = bb0; acc[mt][nt][3] = bb1;
        }
    }
    #pragma unroll
    for (int tap = 0; tap < 9; tap++) {
        const int ky = tap / 3, kx = tap - 3 * ky;
        u32 ah[2][4], al[2][4];
        #pragma unroll
        for (int mt = 0; mt < 2; mt++) {
            int p  = 32 * wm + 16 * mt + rt;
            int c0 = ky * 66 + p + kx;
            int c1 = c0 + 8;
            uint2 A0 = haloS[c0 * 8 + qt];
            uint2 A1 = haloS[c1 * 8 + qt];
            uint2 A2 = haloS[c0 * 8 + qt + 4];
            uint2 A3 = haloS[c1 * 8 + qt + 4];
            ah[mt][0] = A0.x; al[mt][0] = A0.y;
            ah[mt][1] = A1.x; al[mt][1] = A1.y;
            ah[mt][2] = A2.x; al[mt][2] = A2.y;
            ah[mt][3] = A3.x; al[mt][3] = A3.y;
        }
        #pragma unroll
        for (int nt = 0; nt < 4; nt++) {
            uint4 Bv = __ldg(cwB + tap * 512 + nt * 32);
            #pragma unroll
            for (int mt = 0; mt < 2; mt++) {
                mma_bf(acc[mt][nt], ah[mt][0], ah[mt][1], ah[mt][2], ah[mt][3], Bv.x, Bv.y);
                mma_bf(acc[mt][nt], ah[mt][0], ah[mt][1], ah[mt][2], ah[mt][3], Bv.z, Bv.w);
                mma_bf(acc[mt][nt], al[mt][0], al[mt][1], al[mt][2], al[mt][3], Bv.x, Bv.y);
            }
        }
    }
    // h = relu(conv), split, store to hS
    #pragma unroll
    for (int mt = 0; mt < 2; mt++) {
        int r = 32 * wm + 16 * mt + rt;
        #pragma unroll
        for (int nt = 0; nt < 4; nt++) {
            int kp = 16 * wn + 4 * nt + qt;
            float c0 = fmaxf(acc[mt][nt][0], 0.f), c1 = fmaxf(acc[mt][nt][1], 0.f);
            float c2 = fmaxf(acc[mt][nt][2], 0.f), c3 = fmaxf(acc[mt][nt][3], 0.f);
            u32 hi01, lo01, hi23, lo23;
            splitpk(c0, c1, hi01, lo01);
            splitpk(c2, c3, hi23, lo23);
            *(uint2*)(hS + (r * 68 + kp) * 2)       = make_uint2(hi01, lo01);
            *(uint2*)(hS + ((r + 8) * 68 + kp) * 2) = make_uint2(hi23, lo23);
        }
    }
    __syncthreads();   // hS complete; haloS dead (partials may overlay)

    // ================= d1 (k=128, n in 4 quarters) fused with d2 =================
    float acc2[2][2][4];
    #pragma unroll
    for (int mt = 0; mt < 2; mt++)
        #pragma unroll
        for (int nt = 0; nt < 2; nt++)
            #pragma unroll
            for (int e = 0; e < 4; e++) acc2[mt][nt][e] = 0.f;

    #pragma unroll 1
    for (int q = 0; q < 4; q++) {
        float acc1[2][2][4];
        #pragma unroll
        for (int nt = 0; nt < 2; nt++) {
            int n0 = 64 * q + 16 * wn + 8 * nt + 2 * qt;
            float bb0 = __ldg(b1 + n0), bb1 = __ldg(b1 + n0 + 1);
            #pragma unroll
            for (int mt = 0; mt < 2; mt++) {
                acc1[mt][nt][0] = bb0; acc1[mt][nt][1] = bb1;
                acc1[mt][nt][2] = bb0; acc1[mt][nt][3] = bb1;
            }
        }
        #pragma unroll
        for (int kt = 0; kt < 8; kt++) {
            u32 ah[2][4], al[2][4];
            #pragma unroll
            for (int mt = 0; mt < 2; mt++) {
                const u32* hp = hA + mt * 2176 + kt * 16;
                uint2 A0 = *(const uint2*)hp;
                uint2 A1 = *(const uint2*)(hp + 1088);
                uint2 A2 = *(const uint2*)(hp + 8);
                uint2 A3 = *(const uint2*)(hp + 1096);
                ah[mt][0] = A0.x; al[mt][0] = A0.y;
                ah[mt][1] = A1.x; al[mt][1] = A1.y;
                ah[mt][2] = A2.x; al[mt][2] = A2.y;
                ah[mt][3] = A3.x; al[mt][3] = A3.y;
            }
            #pragma unroll
            for (int nt = 0; nt < 2; nt++) {
                uint4 Bv = __ldg(w1B + q * 2048 + kt * 256 + nt * 32);
                #pragma unroll
                for (int mt = 0; mt < 2; mt++) {
                    mma_bf(acc1[mt][nt], ah[mt][0], ah[mt][1], ah[mt][2], ah[mt][3], Bv.x, Bv.y);
                    mma_bf(acc1[mt][nt], ah[mt][0], ah[mt][1], ah[mt][2], ah[mt][3], Bv.z, Bv.w);
                    mma_bf(acc1[mt][nt], al[mt][0], al[mt][1], al[mt][2], al[mt][3], Bv.x, Bv.y);
                }
            }
        }
        // a = relu(acc1) -> register A-frags -> d2 partial MMAs (kt2 = 4q + wn)
        #pragma unroll
        for (int mt = 0; mt < 2; mt++) {
            float* cA = acc1[mt][0];
            float* cB = acc1[mt][1];
            u32 ah0, al0, ah1, al1, ah2, al2, ah3, al3;
            splitpk(fmaxf(cA[0], 0.f), fmaxf(cA[1], 0.f), ah0, al0);
            splitpk(fmaxf(cA[2], 0.f), fmaxf(cA[3], 0.f), ah1, al1);
            splitpk(fmaxf(cB[0], 0.f), fmaxf(cB[1], 0.f), ah2, al2);
            splitpk(fmaxf(cB[2], 0.f), fmaxf(cB[3], 0.f), ah3, al3);
            #pragma unroll
            for (int nt2 = 0; nt2 < 2; nt2++) {
                uint4 Bv = __ldg(w2B + nt2 * 512 + q * 16);
                mma_bf(acc2[mt][nt2], ah0, ah1, ah2, ah3, Bv.x, Bv.y);
                mma_bf(acc2[mt][nt2], ah0, ah1, ah2, ah3, Bv.z, Bv.w);
                mma_bf(acc2[mt][nt2], al0, al1, al2, al3, Bv.x, Bv.y);
            }
        }
    }

    // ---- write d2 partials: part[wn][64][16] (overlays haloS) ----
    #pragma unroll
    for (int mt = 0; mt < 2; mt++) {
        int r = 32 * wm + 16 * mt + rt;
        #pragma unroll
        for (int nt2 = 0; nt2 < 2; nt2++) {
            int n0 = 8 * nt2 + 2 * qt;
            *(float2*)&part[(wn * 64 + r) * 16 + n0] =
                make_float2(acc2[mt][nt2][0], acc2[mt][nt2][1]);
            *(float2*)&part[(wn * 64 + r + 8) * 16 + n0] =
                make_float2(acc2[mt][nt2][2], acc2[mt][nt2][3]);
        }
    }
    __syncthreads();

    // ---- reduce 4 wn partials + masked residual update ----
    {
        int px = tid >> 2;
        int ch0 = (tid & 3) * 4;
        int P = (bI * Hdim + h0) * Wdim + px;
        const float* po = gsrc + (size_t)P * 16;
        float4 o = *(const float4*)(po + ch0);
        bool alive = po[0] > 0.1f;
        float4 d = make_float4(0.f, 0.f, 0.f, 0.f);
        #pragma unroll
        for (int g = 0; g < 4; g++) {
            float4 pv = *(const float4*)&part[(g * 64 + px) * 16 + ch0];
            d.x += pv.x; d.y += pv.y; d.z += pv.z; d.w += pv.w;
        }
        float out[4] = {o.x, o.y, o.z, o.w};
        #pragma unroll
        for (int c = 0; c < 4; c++) {
            int ch = ch0 + c;
            if (ch != 0 && alive) out[c] += (&d.x)[c] + __ldg(b2 + ch);
        }
        *(float4*)(gdst + (size_t)P * 16 + ch0) =
            make_float4(out[0], out[1], out[2], out[3]);
    }
}

__global__ void nca_softmax(float* __restrict__ out) {
    int pix = blockIdx.x * blockDim.x + threadIdx.x;
    if (pix >= NPIX) return;
    const float* g = g_bufs[0] + (size_t)pix * 16;
    float v[10];
    #pragma unroll
    for (int c = 0; c < 10; c++) v[c] = g[1 + c];
    float mx = v[0];
    #pragma unroll
    for (int c = 1; c < 10; c++) mx = fmaxf(mx, v[c]);
    float s = 0.0f;
    #pragma unroll
    for (int c = 0; c < 10; c++) { v[c] = __expf(v[c] - mx); s += v[c]; }
    float inv = 1.0f / s;
    float* o = out + (size_t)pix * 10;
    #pragma unroll
    for (int c = 0; c < 10; c++) o[c] = v[c] * inv;
}

extern "C" void kernel_launch(void* const* d_in, const int* in_sizes, int n_in,
                              void* d_out, int out_size) {
    const float* input = (const float*)d_in[0];
    const float* cw    = (const float*)d_in[1];
    const float* cb    = (const float*)d_in[2];
    const float* w1    = (const float*)d_in[3];
    const float* b1    = (const float*)d_in[4];
    const float* w2    = (const float*)d_in[5];
    const float* b2    = (const float*)d_in[6];

    cudaFuncSetAttribute(nca_step_h, cudaFuncAttributeMaxDynamicSharedMemorySize, SMEM_BYTES);

    nca_prep<<<54, 256>>>(cw, w1, w2);
    nca_init<<<NPIX / 256, 256>>>(input);
    for (int t = 0; t < TSTEPS; t++) {
        nca_step_h<<<Bdim * Hdim, 256, SMEM_BYTES>>>(t & 1, cb, b1, b2);
    }
    nca_softmax<<<NPIX / 256, 256>>>((float*)d_out);
}